// round 12
// baseline (speedup 1.0000x reference)
#include <cuda_runtime.h>
#include <cuda_bf16.h>
#include <cstdint>
#include <math.h>

#define NP 64
#define MM 512
#define DD 256
#define MARGIN 0.2f
#define GRID_SZ 640

__device__ float  g_psum[NP];
__device__ float  g_pcnt[NP];
__device__ float  g_tsort[(size_t)NP * MM * 16];   // per-anchor sorted C values
__device__ float2 g_tsuf [(size_t)NP * MM * 17];   // per-anchor (suffix sum, count)
__device__ int    g_ready[NP * 4];                 // per (part, diag block) flag
__device__ unsigned int g_ticket;                  // last-CTA-done counter
// all zero-initialized at module load; last CTA re-zeros after each launch

// off-diagonal tile map (6 tiles of the 4x4 upper triangle)
__constant__ int c_oby[6] = {0,0,0,1,1,2};
__constant__ int c_obx[6] = {1,2,3,2,3,3};

// ---------------------------------------------------------------------------
__device__ __forceinline__ void split2(float x0, float x1, uint32_t& hi, uint32_t& lo) {
    uint32_t h;
    asm("cvt.rn.bf16x2.f32 %0, %1, %2;" : "=r"(h) : "f"(x1), "f"(x0));
    float h0 = __uint_as_float(h << 16);
    float h1 = __uint_as_float(h & 0xFFFF0000u);
    float r0 = x0 - h0, r1 = x1 - h1;
    asm("cvt.rn.bf16x2.f32 %0, %1, %2;" : "=r"(lo) : "f"(r1), "f"(r0));
    hi = h;
}

#define MMA16816(c0,c1,c2,c3, a0,a1,a2,a3, b0,b1) \
    asm volatile("mma.sync.aligned.m16n8k16.row.col.f32.bf16.bf16.f32 " \
                 "{%0,%1,%2,%3}, {%4,%5,%6,%7}, {%8,%9}, {%0,%1,%2,%3};" \
                 : "+f"(c0), "+f"(c1), "+f"(c2), "+f"(c3) \
                 : "r"(a0), "r"(a1), "r"(a2), "r"(a3), "r"(b0), "r"(b1))

// SMEM layout. Double-buffered mainloop operands [0, 81920); epilogue tables
// overlay that region after the mainloop. Norms/reduce live above.
#define LDA 40
#define TILE_B (128 * LDA * 2)        // 10240 per bf16 tile
#define BUF_B  (4 * TILE_B)           // 40960 per buffer (AHI,ALO,BHI,BLO)
#define OFF_SR  0                     // float [128*17]
#define OFF_TR  8704                  // float2[128*17]
#define OFF_SC  26112                 // float [128*17] (diag: sPos 128*16)
#define OFF_TC  34816                 // float2[128*17] -> 52224
#define OFF_NRM 81920                 // 256 floats -> 82944
#define OFF_RED 82944                 // 16 floats + flag -> 83072
#define SMEM_TOTAL 83072

__device__ __forceinline__ void load_chunk(
    const float* __restrict__ src, int k0, char* smem, int off_hi, int off_lo,
    int tid, float* __restrict__ nacc)
{
    uint16_t* shi = reinterpret_cast<uint16_t*>(smem + off_hi);
    uint16_t* slo = reinterpret_cast<uint16_t*>(smem + off_lo);
#pragma unroll
    for (int it = 0; it < 4; it++) {
        int q   = tid + (it << 8);
        int row = q >> 3;
        int c4  = q & 7;
        float4 v = *reinterpret_cast<const float4*>(src + (size_t)row * DD + k0 + (c4 << 2));
        nacc[it] = fmaf(v.x, v.x, nacc[it]);
        nacc[it] = fmaf(v.y, v.y, nacc[it]);
        nacc[it] = fmaf(v.z, v.z, nacc[it]);
        nacc[it] = fmaf(v.w, v.w, nacc[it]);
        uint32_t h0, h1, l0, l1;
        split2(v.x, v.y, h0, l0);
        split2(v.z, v.w, h1, l1);
        int idx = row * LDA + (c4 << 2);
        *reinterpret_cast<uint2*>(&shi[idx]) = make_uint2(h0, h1);
        *reinterpret_cast<uint2*>(&slo[idx]) = make_uint2(l0, l1);
    }
}

// 4-step scalar binary search with hoisted S[7]/S[15]; idx in [0,16]
__device__ __forceinline__ void search2(
    const float* __restrict__ S, const float2* __restrict__ T,
    float s7, float s15, float d, float& aA, float& aB, float& aC)
{
    int idx = (s7 <= d) ? 8 : 0;
    idx += (S[idx + 3] <= d) ? 4 : 0;
    idx += (S[idx + 1] <= d) ? 2 : 0;
    idx += (S[idx]     <= d) ? 1 : 0;
    idx = (s15 <= d) ? 16 : idx;
    float2 t = T[idx];
    aA += t.x;
    aB  = fmaf(t.y, d, aB);
    aC += t.y;
}

// ---------------------------------------------------------------------------
// fused GEMM + norms + table build (diag) + hinge + last-CTA final reduce.
// 1-D grid of 640: bid<256 diag (p=bid>>2, blk=bid&3); else off-diag.
// ---------------------------------------------------------------------------
__global__ void __launch_bounds__(256, 2) fused_kernel(
    const float* __restrict__ feat, float* __restrict__ out, int out_size)
{
    extern __shared__ char smem[];
    const int tid = threadIdx.x;
    const int w = tid >> 5, lane = tid & 31;
    const int g = lane >> 2, tg = lane & 3;
    const int wm = w >> 1, wn = w & 1;
    const int bid = blockIdx.x;
    const bool diag = (bid < 256);
    int p, by, bx;
    if (diag) {
        p = bid >> 2; by = bx = bid & 3;
    } else {
        int q = bid - 256;
        p = q / 6;
        int t = q - p * 6;
        by = c_oby[t]; bx = c_obx[t];
    }

    float* sNi = reinterpret_cast<float*>(smem + OFF_NRM);
    float* sNj = diag ? sNi : (sNi + 128);

    const float* Abase = feat + ((size_t)p * MM + (size_t)by * 128) * DD;
    const float* Bbase = feat + ((size_t)p * MM + (size_t)bx * 128) * DD;

    float c[2][8][4];
#pragma unroll
    for (int mi = 0; mi < 2; mi++)
#pragma unroll
        for (int ni = 0; ni < 8; ni++)
#pragma unroll
            for (int r = 0; r < 4; r++) c[mi][ni][r] = 0.f;

    float nA[4] = {0.f, 0.f, 0.f, 0.f};
    float nB[4] = {0.f, 0.f, 0.f, 0.f};

    // preload chunk 0 into buffer 0
    load_chunk(Abase, 0, smem, 0, TILE_B, tid, nA);
    if (!diag) load_chunk(Bbase, 0, smem, 2 * TILE_B, 3 * TILE_B, tid, nB);
    __syncthreads();

#pragma unroll 1
    for (int ch = 0; ch < 8; ch++) {
        // issue next chunk's loads into the other buffer (overlaps MMA below)
        if (ch < 7) {
            int bn = ((ch + 1) & 1) * BUF_B;
            int k1 = (ch + 1) << 5;
            load_chunk(Abase, k1, smem, bn, bn + TILE_B, tid, nA);
            if (!diag) load_chunk(Bbase, k1, smem, bn + 2 * TILE_B, bn + 3 * TILE_B, tid, nB);
        }

        const int bc = (ch & 1) * BUF_B;
        const uint16_t* sAhi = reinterpret_cast<const uint16_t*>(smem + bc);
        const uint16_t* sAlo = reinterpret_cast<const uint16_t*>(smem + bc + TILE_B);
        const uint16_t* sBhi = diag ? sAhi : reinterpret_cast<const uint16_t*>(smem + bc + 2 * TILE_B);
        const uint16_t* sBlo = diag ? sAlo : reinterpret_cast<const uint16_t*>(smem + bc + 3 * TILE_B);

#pragma unroll
        for (int ks = 0; ks < 2; ks++) {
            int kk = (ks << 4) + (tg << 1);
            uint32_t ah[2][4], al[2][4];
#pragma unroll
            for (int mi = 0; mi < 2; mi++) {
                int r0 = ((wm << 5) + (mi << 4) + g) * LDA + kk;
                int r1 = r0 + (LDA << 3);
                ah[mi][0] = *reinterpret_cast<const uint32_t*>(&sAhi[r0]);
                ah[mi][1] = *reinterpret_cast<const uint32_t*>(&sAhi[r1]);
                ah[mi][2] = *reinterpret_cast<const uint32_t*>(&sAhi[r0 + 8]);
                ah[mi][3] = *reinterpret_cast<const uint32_t*>(&sAhi[r1 + 8]);
                al[mi][0] = *reinterpret_cast<const uint32_t*>(&sAlo[r0]);
                al[mi][1] = *reinterpret_cast<const uint32_t*>(&sAlo[r1]);
                al[mi][2] = *reinterpret_cast<const uint32_t*>(&sAlo[r0 + 8]);
                al[mi][3] = *reinterpret_cast<const uint32_t*>(&sAlo[r1 + 8]);
            }
            uint32_t bh[8][2], bl[8][2];
#pragma unroll
            for (int ni = 0; ni < 8; ni++) {
                int rb = ((wn << 6) + (ni << 3) + g) * LDA + kk;
                bh[ni][0] = *reinterpret_cast<const uint32_t*>(&sBhi[rb]);
                bh[ni][1] = *reinterpret_cast<const uint32_t*>(&sBhi[rb + 8]);
                bl[ni][0] = *reinterpret_cast<const uint32_t*>(&sBlo[rb]);
                bl[ni][1] = *reinterpret_cast<const uint32_t*>(&sBlo[rb + 8]);
            }
#pragma unroll
            for (int mi = 0; mi < 2; mi++)
#pragma unroll
                for (int ni = 0; ni < 8; ni++) {
                    MMA16816(c[mi][ni][0], c[mi][ni][1], c[mi][ni][2], c[mi][ni][3],
                             ah[mi][0], ah[mi][1], ah[mi][2], ah[mi][3],
                             bh[ni][0], bh[ni][1]);
                    MMA16816(c[mi][ni][0], c[mi][ni][1], c[mi][ni][2], c[mi][ni][3],
                             ah[mi][0], ah[mi][1], ah[mi][2], ah[mi][3],
                             bl[ni][0], bl[ni][1]);
                    MMA16816(c[mi][ni][0], c[mi][ni][1], c[mi][ni][2], c[mi][ni][3],
                             al[mi][0], al[mi][1], al[mi][2], al[mi][3],
                             bh[ni][0], bh[ni][1]);
                }
        }
        __syncthreads();   // next-chunk stores done AND this chunk's reads done
    }

    // norms: row = tid>>3 + 32*it, owned by 8 consecutive lanes -> shfl reduce
#pragma unroll
    for (int it = 0; it < 4; it++) {
        float n = nA[it];
        n += __shfl_xor_sync(0xffffffffu, n, 1);
        n += __shfl_xor_sync(0xffffffffu, n, 2);
        n += __shfl_xor_sync(0xffffffffu, n, 4);
        if ((tid & 7) == 0) sNi[(tid >> 3) + (it << 5)] = n;
        if (!diag) {
            float m = nB[it];
            m += __shfl_xor_sync(0xffffffffu, m, 1);
            m += __shfl_xor_sync(0xffffffffu, m, 2);
            m += __shfl_xor_sync(0xffffffffu, m, 4);
            if ((tid & 7) == 0) sNj[(tid >> 3) + (it << 5)] = m;
        }
    }
    __syncthreads();   // norms visible; operand smem dead -> tables overlay it

    // distances in place of accumulators
#pragma unroll
    for (int mi = 0; mi < 2; mi++) {
        int i0 = (wm << 5) + (mi << 4) + g;
#pragma unroll
        for (int ni = 0; ni < 8; ni++) {
            int j0 = (wn << 6) + (ni << 3) + (tg << 1);
            c[mi][ni][0] = sqrtf(fmaxf(sNi[i0]     + sNj[j0]     - 2.f * c[mi][ni][0], 0.f));
            c[mi][ni][1] = sqrtf(fmaxf(sNi[i0]     + sNj[j0 + 1] - 2.f * c[mi][ni][1], 0.f));
            c[mi][ni][2] = sqrtf(fmaxf(sNi[i0 + 8] + sNj[j0]     - 2.f * c[mi][ni][2], 0.f));
            c[mi][ni][3] = sqrtf(fmaxf(sNi[i0 + 8] + sNj[j0 + 1] - 2.f * c[mi][ni][3], 0.f));
        }
    }

    float*  sSR = reinterpret_cast<float*>(smem + OFF_SR);   // stride 17
    float2* sTR = reinterpret_cast<float2*>(smem + OFF_TR);  // stride 17
    float*  sSC = reinterpret_cast<float*>(smem + OFF_SC);   // stride 17
    float2* sTC = reinterpret_cast<float2*>(smem + OFF_TC);  // stride 17

    if (diag) {
        // scatter same-class C values (classes are 16-aligned: class = idx>>4)
        float* sPos = reinterpret_cast<float*>(smem + OFF_SC);
#pragma unroll
        for (int mi = 0; mi < 2; mi++) {
            int ia = (wm << 5) + (mi << 4) + g, ib = ia + 8;
#pragma unroll
            for (int ni = 0; ni < 8; ni++) {
                int j0 = (wn << 6) + (ni << 3) + (tg << 1);
#pragma unroll
                for (int e = 0; e < 2; e++) {
                    int j = j0 + e;
                    if ((ia >> 4) == (j >> 4)) sPos[(ia << 4) + (j & 15)] = MARGIN + c[mi][ni][e];
                    if ((ib >> 4) == (j >> 4)) sPos[(ib << 4) + (j & 15)] = MARGIN + c[mi][ni][2 + e];
                }
            }
        }
        __syncthreads();
        // per-anchor rank sort + suffix sums; local tables + publish
        if (tid < 128) {
            float v[16];
#pragma unroll
            for (int k = 0; k < 16; k++) v[k] = sPos[(tid << 4) + k];
            float* ss = &sSR[tid * 17];
#pragma unroll
            for (int k = 0; k < 16; k++) {
                float vk = v[k];
                int r = 0;
#pragma unroll
                for (int jj = 0; jj < 16; jj++)
                    r += (int)((v[jj] < vk) | ((v[jj] == vk) & (jj < k)));
                ss[r] = vk;
            }
            size_t ab = (size_t)p * MM + by * 128 + tid;
            float run = 0.f;
            sTR[tid * 17 + 16] = make_float2(0.f, 0.f);
            g_tsuf[ab * 17 + 16] = make_float2(0.f, 0.f);
#pragma unroll
            for (int k = 15; k >= 0; k--) {
                run += ss[k];
                float2 tv = make_float2(run, (float)(16 - k));
                sTR[tid * 17 + k] = tv;
                g_tsuf[ab * 17 + k] = tv;
                g_tsort[ab * 16 + k] = ss[k];
            }
        }
        __threadfence();
        __syncthreads();
        if (tid == 0)
            asm volatile("st.release.gpu.global.b32 [%0], %1;"
                         :: "l"(&g_ready[bid]), "r"(1) : "memory");
    } else {
        // wait for both producer diag CTAs, then load tables
        if (tid == 0) {
            const int* f1 = &g_ready[(p << 2) + by];
            const int* f2 = &g_ready[(p << 2) + bx];
            int r1, r2;
            while (true) {
                asm volatile("ld.acquire.gpu.global.b32 %0, [%1];" : "=r"(r1) : "l"(f1) : "memory");
                asm volatile("ld.acquire.gpu.global.b32 %0, [%1];" : "=r"(r2) : "l"(f2) : "memory");
                if (r1 && r2) break;
                __nanosleep(128);
            }
        }
        __syncthreads();
        size_t rb16 = ((size_t)p * MM + by * 128) * 16;
        size_t rb17 = ((size_t)p * MM + by * 128) * 17;
        size_t cb16 = ((size_t)p * MM + bx * 128) * 16;
        size_t cb17 = ((size_t)p * MM + bx * 128) * 17;
        for (int q = tid; q < 2048; q += 256) {
            sSR[(q >> 4) * 17 + (q & 15)] = g_tsort[rb16 + q];
            sSC[(q >> 4) * 17 + (q & 15)] = g_tsort[cb16 + q];
        }
        for (int q = tid; q < 2176; q += 256) {
            sTR[q] = g_tsuf[rb17 + q];
            sTC[q] = g_tsuf[cb17 + q];
        }
        __syncthreads();
    }

    // hinge searches: row anchors hoisted; col S7/S15 hoisted per column
    const int abase = wm << 5;
    int aIdx[4] = {abase + g, abase + g + 8, abase + 16 + g, abase + 24 + g};
    const float*  SR[4]; const float2* TR[4];
    float S7[4], S15[4];
#pragma unroll
    for (int q = 0; q < 4; q++) {
        SR[q]  = &sSR[aIdx[q] * 17];
        TR[q]  = &sTR[aIdx[q] * 17];
        S7[q]  = SR[q][7];
        S15[q] = SR[q][15];
    }
    float aA = 0.f, aB = 0.f, aC = 0.f;
#pragma unroll
    for (int ni = 0; ni < 8; ni++) {
#pragma unroll
        for (int e = 0; e < 2; e++) {
            int j = (wn << 6) + (ni << 3) + (tg << 1) + e;
            float c7 = 0.f, c15 = 0.f;
            const float* SCj = &sSC[j * 17];
            const float2* TCj = &sTC[j * 17];
            if (!diag) { c7 = SCj[7]; c15 = SCj[15]; }
            int jc = j >> 4;
#pragma unroll
            for (int mi = 0; mi < 2; mi++) {
                float d0 = c[mi][ni][e];
                float d1 = c[mi][ni][2 + e];
                const int q0 = mi << 1, q1 = q0 + 1;
                bool ok0 = !diag || ((aIdx[q0] >> 4) != jc);
                bool ok1 = !diag || ((aIdx[q1] >> 4) != jc);
                if (ok0) search2(SR[q0], TR[q0], S7[q0], S15[q0], d0, aA, aB, aC);
                if (ok1) search2(SR[q1], TR[q1], S7[q1], S15[q1], d1, aA, aB, aC);
                if (!diag) {
                    search2(SCj, TCj, c7, c15, d0, aA, aB, aC);
                    search2(SCj, TCj, c7, c15, d1, aA, aB, aC);
                }
            }
        }
    }

    float loss = aA - aB, cnt = aC;
#pragma unroll
    for (int o = 16; o; o >>= 1) {
        loss += __shfl_xor_sync(0xffffffffu, loss, o);
        cnt  += __shfl_xor_sync(0xffffffffu, cnt, o);
    }
    float* sRed = reinterpret_cast<float*>(smem + OFF_RED);
    int*   sFlag = reinterpret_cast<int*>(smem + OFF_RED + 64);
    if (lane == 0) { sRed[w] = loss; sRed[8 + w] = cnt; }
    __syncthreads();
    if (tid == 0) {
        float L = 0.f, C = 0.f;
#pragma unroll
        for (int k = 0; k < 8; k++) { L += sRed[k]; C += sRed[8 + k]; }
        atomicAdd(&g_psum[p], L);
        atomicAdd(&g_pcnt[p], C);
        __threadfence();
        unsigned int t = atomicAdd(&g_ticket, 1u);
        *sFlag = (t == GRID_SZ - 1u);
    }
    __syncthreads();

    // last CTA: final reduce + write output + reset state for next launch
    if (*sFlag) {
        __threadfence();
        float a = 0.f, b = 0.f;
        if (tid < NP) {
            float cc = g_pcnt[tid], ssum = g_psum[tid];
            a = (cc > 0.f) ? ssum / fmaxf(cc, 1.f) : 0.f;
            b = cc;
        }
#pragma unroll
        for (int o = 16; o; o >>= 1) {
            a += __shfl_xor_sync(0xffffffffu, a, o);
            b += __shfl_xor_sync(0xffffffffu, b, o);
        }
        if (lane == 0 && w < 2) { sRed[w] = a; sRed[2 + w] = b; }
        __syncthreads();
        if (tid == 0) {
            out[0] = (sRed[0] + sRed[1]) / (float)NP;
            if (out_size > 1) out[1] = (sRed[2] + sRed[3]) / (float)NP;
            g_ticket = 0;
        }
        if (tid < NP) { g_psum[tid] = 0.f; g_pcnt[tid] = 0.f; }
        g_ready[tid] = 0;
    }
}

extern "C" void kernel_launch(void* const* d_in, const int* in_sizes, int n_in,
                              void* d_out, int out_size) {
    const float* feat = (const float*)d_in[0];
    (void)in_sizes; (void)n_in;

    cudaFuncSetAttribute(fused_kernel, cudaFuncAttributeMaxDynamicSharedMemorySize, SMEM_TOTAL);

    fused_kernel<<<GRID_SZ, 256, SMEM_TOTAL>>>(feat, (float*)d_out, out_size);
}

// round 13
// speedup vs baseline: 1.0187x; 1.0187x over previous
#include <cuda_runtime.h>
#include <cuda_bf16.h>
#include <cstdint>
#include <math.h>

#define NP 64
#define MM 512
#define DD 256
#define MARGIN 0.2f
#define GRID_SZ 640

__device__ float  g_psum[NP];
__device__ float  g_pcnt[NP];
__device__ float  g_norm[NP * MM];
__device__ float  g_tsort[(size_t)NP * MM * 16];   // per-anchor sorted C values
__device__ float2 g_tsuf [(size_t)NP * MM * 17];   // per-anchor (suffix sum, count)
__device__ int    g_ready[NP * 4];                 // per (part, diag block) flag
__device__ unsigned int g_ticket;                  // last-CTA-done counter
// pre-split bf16 feature arrays (16 MB each)
__device__ __align__(16) uint16_t g_hi[(size_t)NP * MM * DD];
__device__ __align__(16) uint16_t g_lo[(size_t)NP * MM * DD];

// off-diagonal tile map (6 tiles of the 4x4 upper triangle)
__constant__ int c_oby[6] = {0,0,0,1,1,2};
__constant__ int c_obx[6] = {1,2,3,2,3,3};

// ---------------------------------------------------------------------------
__device__ __forceinline__ void split2(float x0, float x1, uint32_t& hi, uint32_t& lo) {
    uint32_t h;
    asm("cvt.rn.bf16x2.f32 %0, %1, %2;" : "=r"(h) : "f"(x1), "f"(x0));
    float h0 = __uint_as_float(h << 16);
    float h1 = __uint_as_float(h & 0xFFFF0000u);
    float r0 = x0 - h0, r1 = x1 - h1;
    asm("cvt.rn.bf16x2.f32 %0, %1, %2;" : "=r"(lo) : "f"(r1), "f"(r0));
    hi = h;
}

__device__ __forceinline__ uint32_t smem_u32(const void* p) {
    uint32_t a;
    asm("{ .reg .u64 t; cvta.to.shared.u64 t, %1; cvt.u32.u64 %0, t; }" : "=r"(a) : "l"(p));
    return a;
}

// ---------------------------------------------------------------------------
// prep: one pass over feat -> g_hi/g_lo bf16 splits + row norms.
// 4096 blocks x 256 threads; one warp per row (8 rows/block).
// ---------------------------------------------------------------------------
__global__ __launch_bounds__(256) void prep_kernel(const float* __restrict__ feat) {
    int row  = (blockIdx.x << 3) + (threadIdx.x >> 5);
    int lane = threadIdx.x & 31;
    const float4* f = reinterpret_cast<const float4*>(feat + (size_t)row * DD);
    float4 v0 = f[lane << 1], v1 = f[(lane << 1) + 1];   // k = lane*8 .. +7
    uint32_t h0, h1, h2, h3, l0, l1, l2, l3;
    split2(v0.x, v0.y, h0, l0); split2(v0.z, v0.w, h1, l1);
    split2(v1.x, v1.y, h2, l2); split2(v1.z, v1.w, h3, l3);
    size_t o = (size_t)row * DD + (lane << 3);
    *reinterpret_cast<uint4*>(g_hi + o) = make_uint4(h0, h1, h2, h3);
    *reinterpret_cast<uint4*>(g_lo + o) = make_uint4(l0, l1, l2, l3);
    float s = v0.x*v0.x + v0.y*v0.y + v0.z*v0.z + v0.w*v0.w
            + v1.x*v1.x + v1.y*v1.y + v1.z*v1.z + v1.w*v1.w;
#pragma unroll
    for (int ofs = 16; ofs; ofs >>= 1) s += __shfl_xor_sync(0xffffffffu, s, ofs);
    if (lane == 0) g_norm[row] = s;
}

#define MMA16816(c0,c1,c2,c3, a0,a1,a2,a3, b0,b1) \
    asm volatile("mma.sync.aligned.m16n8k16.row.col.f32.bf16.bf16.f32 " \
                 "{%0,%1,%2,%3}, {%4,%5,%6,%7}, {%8,%9}, {%0,%1,%2,%3};" \
                 : "+f"(c0), "+f"(c1), "+f"(c2), "+f"(c3) \
                 : "r"(a0), "r"(a1), "r"(a2), "r"(a3), "r"(b0), "r"(b1))

// SMEM layout. Double-buffered mainloop operands [0, 81920); epilogue tables
// overlay that region after the mainloop. Norms/reduce live above.
#define LDA 40
#define TILE_B (128 * LDA * 2)        // 10240 per bf16 tile
#define BUF_B  (4 * TILE_B)           // 40960 per buffer (AHI,ALO,BHI,BLO)
#define OFF_SR  0                     // float [128*17]
#define OFF_TR  8704                  // float2[128*17]
#define OFF_SC  26112                 // float [128*17] (diag: sPos 128*16)
#define OFF_TC  34816                 // float2[128*17] -> 52224
#define OFF_NRM 81920                 // 256 floats -> 82944
#define OFF_RED 82944                 // 16 floats + flag -> 83072
#define SMEM_TOTAL 83072

// stage one 128x32 bf16 tile (already split) global -> smem via cp.async
__device__ __forceinline__ void stage_tile(
    uint32_t sbase, const uint16_t* __restrict__ gsrc, int k0, int tid)
{
#pragma unroll
    for (int i = 0; i < 2; i++) {
        int id  = tid + (i << 8);       // 0..511 16B chunks
        int row = id >> 2, c = id & 3;
        uint32_t sa = sbase + row * (LDA * 2) + (c << 4);
        const void* ga = gsrc + (size_t)row * DD + k0 + (c << 3);
        asm volatile("cp.async.cg.shared.global [%0], [%1], 16;"
                     :: "r"(sa), "l"(ga) : "memory");
    }
}

// 4-step scalar binary search with hoisted S[7]/S[15]; idx in [0,16]
__device__ __forceinline__ void search2(
    const float* __restrict__ S, const float2* __restrict__ T,
    float s7, float s15, float d, float& aA, float& aB, float& aC)
{
    int idx = (s7 <= d) ? 8 : 0;
    idx += (S[idx + 3] <= d) ? 4 : 0;
    idx += (S[idx + 1] <= d) ? 2 : 0;
    idx += (S[idx]     <= d) ? 1 : 0;
    idx = (s15 <= d) ? 16 : idx;
    float2 t = T[idx];
    aA += t.x;
    aB  = fmaf(t.y, d, aB);
    aC += t.y;
}

// ---------------------------------------------------------------------------
// fused GEMM (pre-split bf16 via cp.async) + table build (diag) + hinge +
// last-CTA final reduce. 1-D grid 640: bid<256 diag; else off-diag.
// ---------------------------------------------------------------------------
__global__ void __launch_bounds__(256, 2) fused_kernel(
    float* __restrict__ out, int out_size)
{
    extern __shared__ char smem[];
    const int tid = threadIdx.x;
    const int w = tid >> 5, lane = tid & 31;
    const int g = lane >> 2, tg = lane & 3;
    const int wm = w >> 1, wn = w & 1;
    const int bid = blockIdx.x;
    const bool diag = (bid < 256);
    int p, by, bx;
    if (diag) {
        p = bid >> 2; by = bx = bid & 3;
    } else {
        int q = bid - 256;
        p = q / 6;
        int t = q - p * 6;
        by = c_oby[t]; bx = c_obx[t];
    }
    const uint32_t sb = smem_u32(smem);

    float* sNi = reinterpret_cast<float*>(smem + OFF_NRM);
    float* sNj = diag ? sNi : (sNi + 128);
    if (tid < 128) {
        sNi[tid] = g_norm[p * MM + by * 128 + tid];
        if (!diag) sNj[tid] = g_norm[p * MM + bx * 128 + tid];
    }

    const size_t Aoff = ((size_t)p * MM + (size_t)by * 128) * DD;
    const size_t Boff = ((size_t)p * MM + (size_t)bx * 128) * DD;
    const uint16_t* Ahi = g_hi + Aoff;
    const uint16_t* Alo = g_lo + Aoff;
    const uint16_t* Bhi = g_hi + Boff;
    const uint16_t* Blo = g_lo + Boff;

    float c[2][8][4];
#pragma unroll
    for (int mi = 0; mi < 2; mi++)
#pragma unroll
        for (int ni = 0; ni < 8; ni++)
#pragma unroll
            for (int r = 0; r < 4; r++) c[mi][ni][r] = 0.f;

    // preload chunk 0 into buffer 0
    stage_tile(sb, Ahi, 0, tid);
    stage_tile(sb + TILE_B, Alo, 0, tid);
    if (!diag) {
        stage_tile(sb + 2 * TILE_B, Bhi, 0, tid);
        stage_tile(sb + 3 * TILE_B, Blo, 0, tid);
    }
    asm volatile("cp.async.commit_group;" ::: "memory");

#pragma unroll 1
    for (int ch = 0; ch < 8; ch++) {
        if (ch < 7) {
            uint32_t bn = sb + ((ch + 1) & 1) * BUF_B;
            int k1 = (ch + 1) << 5;
            stage_tile(bn, Ahi, k1, tid);
            stage_tile(bn + TILE_B, Alo, k1, tid);
            if (!diag) {
                stage_tile(bn + 2 * TILE_B, Bhi, k1, tid);
                stage_tile(bn + 3 * TILE_B, Blo, k1, tid);
            }
            asm volatile("cp.async.commit_group;" ::: "memory");
            asm volatile("cp.async.wait_group 1;" ::: "memory");
        } else {
            asm volatile("cp.async.wait_group 0;" ::: "memory");
        }
        __syncthreads();   // chunk ch landed for all threads

        const int bc = (ch & 1) * BUF_B;
        const uint16_t* sAhi = reinterpret_cast<const uint16_t*>(smem + bc);
        const uint16_t* sAlo = reinterpret_cast<const uint16_t*>(smem + bc + TILE_B);
        const uint16_t* sBhi = diag ? sAhi : reinterpret_cast<const uint16_t*>(smem + bc + 2 * TILE_B);
        const uint16_t* sBlo = diag ? sAlo : reinterpret_cast<const uint16_t*>(smem + bc + 3 * TILE_B);

#pragma unroll
        for (int ks = 0; ks < 2; ks++) {
            int kk = (ks << 4) + (tg << 1);
            uint32_t ah[2][4], al[2][4];
#pragma unroll
            for (int mi = 0; mi < 2; mi++) {
                int r0 = ((wm << 5) + (mi << 4) + g) * LDA + kk;
                int r1 = r0 + (LDA << 3);
                ah[mi][0] = *reinterpret_cast<const uint32_t*>(&sAhi[r0]);
                ah[mi][1] = *reinterpret_cast<const uint32_t*>(&sAhi[r1]);
                ah[mi][2] = *reinterpret_cast<const uint32_t*>(&sAhi[r0 + 8]);
                ah[mi][3] = *reinterpret_cast<const uint32_t*>(&sAhi[r1 + 8]);
                al[mi][0] = *reinterpret_cast<const uint32_t*>(&sAlo[r0]);
                al[mi][1] = *reinterpret_cast<const uint32_t*>(&sAlo[r1]);
                al[mi][2] = *reinterpret_cast<const uint32_t*>(&sAlo[r0 + 8]);
                al[mi][3] = *reinterpret_cast<const uint32_t*>(&sAlo[r1 + 8]);
            }
            uint32_t bh[8][2], bl[8][2];
#pragma unroll
            for (int ni = 0; ni < 8; ni++) {
                int rb = ((wn << 6) + (ni << 3) + g) * LDA + kk;
                bh[ni][0] = *reinterpret_cast<const uint32_t*>(&sBhi[rb]);
                bh[ni][1] = *reinterpret_cast<const uint32_t*>(&sBhi[rb + 8]);
                bl[ni][0] = *reinterpret_cast<const uint32_t*>(&sBlo[rb]);
                bl[ni][1] = *reinterpret_cast<const uint32_t*>(&sBlo[rb + 8]);
            }
#pragma unroll
            for (int mi = 0; mi < 2; mi++)
#pragma unroll
                for (int ni = 0; ni < 8; ni++) {
                    MMA16816(c[mi][ni][0], c[mi][ni][1], c[mi][ni][2], c[mi][ni][3],
                             ah[mi][0], ah[mi][1], ah[mi][2], ah[mi][3],
                             bh[ni][0], bh[ni][1]);
                    MMA16816(c[mi][ni][0], c[mi][ni][1], c[mi][ni][2], c[mi][ni][3],
                             ah[mi][0], ah[mi][1], ah[mi][2], ah[mi][3],
                             bl[ni][0], bl[ni][1]);
                    MMA16816(c[mi][ni][0], c[mi][ni][1], c[mi][ni][2], c[mi][ni][3],
                             al[mi][0], al[mi][1], al[mi][2], al[mi][3],
                             bh[ni][0], bh[ni][1]);
                }
        }
        __syncthreads();   // all reads of buf[ch&1] done before it is re-staged
    }

    // distances in place of accumulators
#pragma unroll
    for (int mi = 0; mi < 2; mi++) {
        int i0 = (wm << 5) + (mi << 4) + g;
#pragma unroll
        for (int ni = 0; ni < 8; ni++) {
            int j0 = (wn << 6) + (ni << 3) + (tg << 1);
            c[mi][ni][0] = sqrtf(fmaxf(sNi[i0]     + sNj[j0]     - 2.f * c[mi][ni][0], 0.f));
            c[mi][ni][1] = sqrtf(fmaxf(sNi[i0]     + sNj[j0 + 1] - 2.f * c[mi][ni][1], 0.f));
            c[mi][ni][2] = sqrtf(fmaxf(sNi[i0 + 8] + sNj[j0]     - 2.f * c[mi][ni][2], 0.f));
            c[mi][ni][3] = sqrtf(fmaxf(sNi[i0 + 8] + sNj[j0 + 1] - 2.f * c[mi][ni][3], 0.f));
        }
    }

    float*  sSR = reinterpret_cast<float*>(smem + OFF_SR);   // stride 17
    float2* sTR = reinterpret_cast<float2*>(smem + OFF_TR);  // stride 17
    float*  sSC = reinterpret_cast<float*>(smem + OFF_SC);   // stride 17
    float2* sTC = reinterpret_cast<float2*>(smem + OFF_TC);  // stride 17

    if (diag) {
        // scatter same-class C values (classes are 16-aligned: class = idx>>4)
        float* sPos = reinterpret_cast<float*>(smem + OFF_SC);
#pragma unroll
        for (int mi = 0; mi < 2; mi++) {
            int ia = (wm << 5) + (mi << 4) + g, ib = ia + 8;
#pragma unroll
            for (int ni = 0; ni < 8; ni++) {
                int j0 = (wn << 6) + (ni << 3) + (tg << 1);
#pragma unroll
                for (int e = 0; e < 2; e++) {
                    int j = j0 + e;
                    if ((ia >> 4) == (j >> 4)) sPos[(ia << 4) + (j & 15)] = MARGIN + c[mi][ni][e];
                    if ((ib >> 4) == (j >> 4)) sPos[(ib << 4) + (j & 15)] = MARGIN + c[mi][ni][2 + e];
                }
            }
        }
        __syncthreads();
        // per-anchor rank sort + suffix sums; local tables + publish
        if (tid < 128) {
            float v[16];
#pragma unroll
            for (int k = 0; k < 16; k++) v[k] = sPos[(tid << 4) + k];
            float* ss = &sSR[tid * 17];
#pragma unroll
            for (int k = 0; k < 16; k++) {
                float vk = v[k];
                int r = 0;
#pragma unroll
                for (int jj = 0; jj < 16; jj++)
                    r += (int)((v[jj] < vk) | ((v[jj] == vk) & (jj < k)));
                ss[r] = vk;
            }
            size_t ab = (size_t)p * MM + by * 128 + tid;
            float run = 0.f;
            sTR[tid * 17 + 16] = make_float2(0.f, 0.f);
            g_tsuf[ab * 17 + 16] = make_float2(0.f, 0.f);
#pragma unroll
            for (int k = 15; k >= 0; k--) {
                run += ss[k];
                float2 tv = make_float2(run, (float)(16 - k));
                sTR[tid * 17 + k] = tv;
                g_tsuf[ab * 17 + k] = tv;
                g_tsort[ab * 16 + k] = ss[k];
            }
        }
        __threadfence();
        __syncthreads();
        if (tid == 0)
            asm volatile("st.release.gpu.global.b32 [%0], %1;"
                         :: "l"(&g_ready[bid]), "r"(1) : "memory");
    } else {
        // wait for both producer diag CTAs, then load tables
        if (tid == 0) {
            const int* f1 = &g_ready[(p << 2) + by];
            const int* f2 = &g_ready[(p << 2) + bx];
            int r1, r2;
            while (true) {
                asm volatile("ld.acquire.gpu.global.b32 %0, [%1];" : "=r"(r1) : "l"(f1) : "memory");
                asm volatile("ld.acquire.gpu.global.b32 %0, [%1];" : "=r"(r2) : "l"(f2) : "memory");
                if (r1 && r2) break;
                __nanosleep(128);
            }
        }
        __syncthreads();
        size_t rb16 = ((size_t)p * MM + by * 128) * 16;
        size_t rb17 = ((size_t)p * MM + by * 128) * 17;
        size_t cb16 = ((size_t)p * MM + bx * 128) * 16;
        size_t cb17 = ((size_t)p * MM + bx * 128) * 17;
        for (int q = tid; q < 2048; q += 256) {
            sSR[(q >> 4) * 17 + (q & 15)] = g_tsort[rb16 + q];
            sSC[(q >> 4) * 17 + (q & 15)] = g_tsort[cb16 + q];
        }
        for (int q = tid; q < 2176; q += 256) {
            sTR[q] = g_tsuf[rb17 + q];
            sTC[q] = g_tsuf[cb17 + q];
        }
        __syncthreads();
    }

    // hinge searches: row anchors hoisted; col S7/S15 hoisted per column
    const int abase = wm << 5;
    int aIdx[4] = {abase + g, abase + g + 8, abase + 16 + g, abase + 24 + g};
    const float*  SR[4]; const float2* TR[4];
    float S7[4], S15[4];
#pragma unroll
    for (int q = 0; q < 4; q++) {
        SR[q]  = &sSR[aIdx[q] * 17];
        TR[q]  = &sTR[aIdx[q] * 17];
        S7[q]  = SR[q][7];
        S15[q] = SR[q][15];
    }
    float aA = 0.f, aB = 0.f, aC = 0.f;
#pragma unroll
    for (int ni = 0; ni < 8; ni++) {
#pragma unroll
        for (int e = 0; e < 2; e++) {
            int j = (wn << 6) + (ni << 3) + (tg << 1) + e;
            float c7 = 0.f, c15 = 0.f;
            const float* SCj = &sSC[j * 17];
            const float2* TCj = &sTC[j * 17];
            if (!diag) { c7 = SCj[7]; c15 = SCj[15]; }
            int jc = j >> 4;
#pragma unroll
            for (int mi = 0; mi < 2; mi++) {
                float d0 = c[mi][ni][e];
                float d1 = c[mi][ni][2 + e];
                const int q0 = mi << 1, q1 = q0 + 1;
                bool ok0 = !diag || ((aIdx[q0] >> 4) != jc);
                bool ok1 = !diag || ((aIdx[q1] >> 4) != jc);
                if (ok0) search2(SR[q0], TR[q0], S7[q0], S15[q0], d0, aA, aB, aC);
                if (ok1) search2(SR[q1], TR[q1], S7[q1], S15[q1], d1, aA, aB, aC);
                if (!diag) {
                    search2(SCj, TCj, c7, c15, d0, aA, aB, aC);
                    search2(SCj, TCj, c7, c15, d1, aA, aB, aC);
                }
            }
        }
    }

    float loss = aA - aB, cnt = aC;
#pragma unroll
    for (int o = 16; o; o >>= 1) {
        loss += __shfl_xor_sync(0xffffffffu, loss, o);
        cnt  += __shfl_xor_sync(0xffffffffu, cnt, o);
    }
    float* sRed = reinterpret_cast<float*>(smem + OFF_RED);
    int*   sFlag = reinterpret_cast<int*>(smem + OFF_RED + 64);
    if (lane == 0) { sRed[w] = loss; sRed[8 + w] = cnt; }
    __syncthreads();
    if (tid == 0) {
        float L = 0.f, C = 0.f;
#pragma unroll
        for (int k = 0; k < 8; k++) { L += sRed[k]; C += sRed[8 + k]; }
        atomicAdd(&g_psum[p], L);
        atomicAdd(&g_pcnt[p], C);
        __threadfence();
        unsigned int t = atomicAdd(&g_ticket, 1u);
        *sFlag = (t == GRID_SZ - 1u);
    }
    __syncthreads();

    // last CTA: final reduce + write output + reset state for next launch
    if (*sFlag) {
        __threadfence();
        float a = 0.f, b = 0.f;
        if (tid < NP) {
            float cc = g_pcnt[tid], ssum = g_psum[tid];
            a = (cc > 0.f) ? ssum / fmaxf(cc, 1.f) : 0.f;
            b = cc;
        }
#pragma unroll
        for (int o = 16; o; o >>= 1) {
            a += __shfl_xor_sync(0xffffffffu, a, o);
            b += __shfl_xor_sync(0xffffffffu, b, o);
        }
        if (lane == 0 && w < 2) { sRed[w] = a; sRed[2 + w] = b; }
        __syncthreads();
        if (tid == 0) {
            out[0] = (sRed[0] + sRed[1]) / (float)NP;
            if (out_size > 1) out[1] = (sRed[2] + sRed[3]) / (float)NP;
            g_ticket = 0;
        }
        if (tid < NP) { g_psum[tid] = 0.f; g_pcnt[tid] = 0.f; }
        g_ready[tid] = 0;
    }
}

extern "C" void kernel_launch(void* const* d_in, const int* in_sizes, int n_in,
                              void* d_out, int out_size) {
    const float* feat = (const float*)d_in[0];
    (void)in_sizes; (void)n_in;

    cudaFuncSetAttribute(fused_kernel, cudaFuncAttributeMaxDynamicSharedMemorySize, SMEM_TOTAL);

    prep_kernel<<<4096, 256>>>(feat);
    fused_kernel<<<GRID_SZ, 256, SMEM_TOTAL>>>((float*)d_out, out_size);
}

// round 14
// speedup vs baseline: 1.0202x; 1.0014x over previous
#include <cuda_runtime.h>
#include <cuda_bf16.h>
#include <cstdint>
#include <math.h>

#define NP 64
#define MM 512
#define DD 256
#define MARGIN 0.2f
#define GRID_SZ 640

__device__ float  g_psum[NP];
__device__ float  g_pcnt[NP];
__device__ float  g_norm[NP * MM];
__device__ float  g_tsort[(size_t)NP * MM * 16];   // per-anchor sorted C values
__device__ float2 g_tsuf [(size_t)NP * MM * 17];   // per-anchor (suffix sum, count)
__device__ int    g_ready[NP * 4];                 // per (part, diag block) flag
__device__ unsigned int g_ticket;                  // last-CTA-done counter
// pre-split bf16 feature arrays (16 MB each)
__device__ __align__(16) uint16_t g_hi[(size_t)NP * MM * DD];
__device__ __align__(16) uint16_t g_lo[(size_t)NP * MM * DD];

// off-diagonal tile map (6 tiles of the 4x4 upper triangle)
__constant__ int c_oby[6] = {0,0,0,1,1,2};
__constant__ int c_obx[6] = {1,2,3,2,3,3};

// ---------------------------------------------------------------------------
__device__ __forceinline__ void split2(float x0, float x1, uint32_t& hi, uint32_t& lo) {
    uint32_t h;
    asm("cvt.rn.bf16x2.f32 %0, %1, %2;" : "=r"(h) : "f"(x1), "f"(x0));
    float h0 = __uint_as_float(h << 16);
    float h1 = __uint_as_float(h & 0xFFFF0000u);
    float r0 = x0 - h0, r1 = x1 - h1;
    asm("cvt.rn.bf16x2.f32 %0, %1, %2;" : "=r"(lo) : "f"(r1), "f"(r0));
    hi = h;
}

__device__ __forceinline__ uint32_t smem_u32(const void* p) {
    uint32_t a;
    asm("{ .reg .u64 t; cvta.to.shared.u64 t, %1; cvt.u32.u64 %0, t; }" : "=r"(a) : "l"(p));
    return a;
}

// ---------------------------------------------------------------------------
// prep: one pass over feat -> g_hi/g_lo bf16 splits + row norms.
// ---------------------------------------------------------------------------
__global__ __launch_bounds__(256) void prep_kernel(const float* __restrict__ feat) {
    int row  = (blockIdx.x << 3) + (threadIdx.x >> 5);
    int lane = threadIdx.x & 31;
    const float4* f = reinterpret_cast<const float4*>(feat + (size_t)row * DD);
    float4 v0 = f[lane << 1], v1 = f[(lane << 1) + 1];
    uint32_t h0, h1, h2, h3, l0, l1, l2, l3;
    split2(v0.x, v0.y, h0, l0); split2(v0.z, v0.w, h1, l1);
    split2(v1.x, v1.y, h2, l2); split2(v1.z, v1.w, h3, l3);
    size_t o = (size_t)row * DD + (lane << 3);
    *reinterpret_cast<uint4*>(g_hi + o) = make_uint4(h0, h1, h2, h3);
    *reinterpret_cast<uint4*>(g_lo + o) = make_uint4(l0, l1, l2, l3);
    float s = v0.x*v0.x + v0.y*v0.y + v0.z*v0.z + v0.w*v0.w
            + v1.x*v1.x + v1.y*v1.y + v1.z*v1.z + v1.w*v1.w;
#pragma unroll
    for (int ofs = 16; ofs; ofs >>= 1) s += __shfl_xor_sync(0xffffffffu, s, ofs);
    if (lane == 0) g_norm[row] = s;
}

#define MMA16816(c0,c1,c2,c3, a0,a1,a2,a3, b0,b1) \
    asm volatile("mma.sync.aligned.m16n8k16.row.col.f32.bf16.bf16.f32 " \
                 "{%0,%1,%2,%3}, {%4,%5,%6,%7}, {%8,%9}, {%0,%1,%2,%3};" \
                 : "+f"(c0), "+f"(c1), "+f"(c2), "+f"(c3) \
                 : "r"(a0), "r"(a1), "r"(a2), "r"(a3), "r"(b0), "r"(b1))

#define LDSM_X4(r0,r1,r2,r3, addr) \
    asm volatile("ldmatrix.sync.aligned.m8n8.x4.shared.b16 {%0,%1,%2,%3}, [%4];" \
        : "=r"(r0), "=r"(r1), "=r"(r2), "=r"(r3) : "r"(addr))

// SMEM layout. Double-buffered mainloop operands [0, 81920); epilogue tables
// overlay that region after the mainloop. Norms/reduce live above.
#define LDA 40
#define TILE_B (128 * LDA * 2)        // 10240 per bf16 tile
#define BUF_B  (4 * TILE_B)           // 40960 per buffer (AHI,ALO,BHI,BLO)
#define OFF_SR  0                     // float [128*17]
#define OFF_TR  8704                  // float2[128*17]
#define OFF_SC  26112                 // float [128*17] (diag: sPos 128*16)
#define OFF_TC  34816                 // float2[128*17] -> 52224
#define OFF_NRM 81920                 // 256 floats -> 82944
#define OFF_RED 82944                 // 16 floats + flag -> 83072
#define SMEM_TOTAL 83072

// stage one 128x32 bf16 tile (already split) global -> smem via cp.async
__device__ __forceinline__ void stage_tile(
    uint32_t sbase, const uint16_t* __restrict__ gsrc, int k0, int tid)
{
#pragma unroll
    for (int i = 0; i < 2; i++) {
        int id  = tid + (i << 8);       // 0..511 16B chunks
        int row = id >> 2, c = id & 3;
        uint32_t sa = sbase + row * (LDA * 2) + (c << 4);
        const void* ga = gsrc + (size_t)row * DD + k0 + (c << 3);
        asm volatile("cp.async.cg.shared.global [%0], [%1], 16;"
                     :: "r"(sa), "l"(ga) : "memory");
    }
}

// 4-step scalar binary search with hoisted S[7]/S[15]; idx in [0,16]
__device__ __forceinline__ void search2(
    const float* __restrict__ S, const float2* __restrict__ T,
    float s7, float s15, float d, float& aA, float& aB, float& aC)
{
    int idx = (s7 <= d) ? 8 : 0;
    idx += (S[idx + 3] <= d) ? 4 : 0;
    idx += (S[idx + 1] <= d) ? 2 : 0;
    idx += (S[idx]     <= d) ? 1 : 0;
    idx = (s15 <= d) ? 16 : idx;
    float2 t = T[idx];
    aA += t.x;
    aB  = fmaf(t.y, d, aB);
    aC += t.y;
}

// ---------------------------------------------------------------------------
// fused GEMM (pre-split bf16, cp.async + ldmatrix) + table build (diag) +
// hinge + last-CTA final reduce. 1-D grid 640: bid<256 diag; else off-diag.
// ---------------------------------------------------------------------------
__global__ void __launch_bounds__(256, 2) fused_kernel(
    float* __restrict__ out, int out_size)
{
    extern __shared__ char smem[];
    const int tid = threadIdx.x;
    const int w = tid >> 5, lane = tid & 31;
    const int g = lane >> 2, tg = lane & 3;
    const int wm = w >> 1, wn = w & 1;
    const int bid = blockIdx.x;
    const bool diag = (bid < 256);
    int p, by, bx;
    if (diag) {
        p = bid >> 2; by = bx = bid & 3;
    } else {
        int q = bid - 256;
        p = q / 6;
        int t = q - p * 6;
        by = c_oby[t]; bx = c_obx[t];
    }
    const uint32_t sb = smem_u32(smem);

    float* sNi = reinterpret_cast<float*>(smem + OFF_NRM);
    float* sNj = diag ? sNi : (sNi + 128);
    if (tid < 128) {
        sNi[tid] = g_norm[p * MM + by * 128 + tid];
        if (!diag) sNj[tid] = g_norm[p * MM + bx * 128 + tid];
    }

    const size_t Aoff = ((size_t)p * MM + (size_t)by * 128) * DD;
    const size_t Boff = ((size_t)p * MM + (size_t)bx * 128) * DD;
    const uint16_t* Ahi = g_hi + Aoff;
    const uint16_t* Alo = g_lo + Aoff;
    const uint16_t* Bhi = g_hi + Boff;
    const uint16_t* Blo = g_lo + Boff;

    // ldmatrix per-lane offsets (bytes within a tile)
    const int aRowOff = ((wm << 5) + (lane & 15)) * (LDA * 2)
                      + ((lane & 16) ? 16 : 0);
    const int bRowOff = ((wn << 6) + (lane & 7) + ((lane & 16) ? 8 : 0)) * (LDA * 2)
                      + ((lane & 8) ? 16 : 0);

    float c[2][8][4];
#pragma unroll
    for (int mi = 0; mi < 2; mi++)
#pragma unroll
        for (int ni = 0; ni < 8; ni++)
#pragma unroll
            for (int r = 0; r < 4; r++) c[mi][ni][r] = 0.f;

    // preload chunk 0 into buffer 0
    stage_tile(sb, Ahi, 0, tid);
    stage_tile(sb + TILE_B, Alo, 0, tid);
    if (!diag) {
        stage_tile(sb + 2 * TILE_B, Bhi, 0, tid);
        stage_tile(sb + 3 * TILE_B, Blo, 0, tid);
    }
    asm volatile("cp.async.commit_group;" ::: "memory");

#pragma unroll 1
    for (int ch = 0; ch < 8; ch++) {
        if (ch < 7) {
            uint32_t bn = sb + ((ch + 1) & 1) * BUF_B;
            int k1 = (ch + 1) << 5;
            stage_tile(bn, Ahi, k1, tid);
            stage_tile(bn + TILE_B, Alo, k1, tid);
            if (!diag) {
                stage_tile(bn + 2 * TILE_B, Bhi, k1, tid);
                stage_tile(bn + 3 * TILE_B, Blo, k1, tid);
            }
            asm volatile("cp.async.commit_group;" ::: "memory");
            asm volatile("cp.async.wait_group 1;" ::: "memory");
        } else {
            asm volatile("cp.async.wait_group 0;" ::: "memory");
        }
        __syncthreads();   // chunk ch landed for all threads

        const uint32_t bA = sb + (ch & 1) * BUF_B;
        const uint32_t bB = diag ? bA : (bA + 2 * TILE_B);

#pragma unroll
        for (int ks = 0; ks < 2; ks++) {
            const int kOff = ks << 5;   // 32 bytes per k-step
            uint32_t ah[2][4], al[2][4];
#pragma unroll
            for (int mi = 0; mi < 2; mi++) {
                uint32_t aa = bA + aRowOff + mi * (16 * LDA * 2) + kOff;
                LDSM_X4(ah[mi][0], ah[mi][1], ah[mi][2], ah[mi][3], aa);
                LDSM_X4(al[mi][0], al[mi][1], al[mi][2], al[mi][3], aa + TILE_B);
            }
            uint32_t bh[8][2], bl[8][2];
#pragma unroll
            for (int n2 = 0; n2 < 4; n2++) {
                uint32_t ba = bB + bRowOff + n2 * (16 * LDA * 2) + kOff;
                LDSM_X4(bh[2*n2][0], bh[2*n2][1], bh[2*n2+1][0], bh[2*n2+1][1], ba);
                LDSM_X4(bl[2*n2][0], bl[2*n2][1], bl[2*n2+1][0], bl[2*n2+1][1], ba + TILE_B);
            }
#pragma unroll
            for (int mi = 0; mi < 2; mi++)
#pragma unroll
                for (int ni = 0; ni < 8; ni++) {
                    MMA16816(c[mi][ni][0], c[mi][ni][1], c[mi][ni][2], c[mi][ni][3],
                             ah[mi][0], ah[mi][1], ah[mi][2], ah[mi][3],
                             bh[ni][0], bh[ni][1]);
                    MMA16816(c[mi][ni][0], c[mi][ni][1], c[mi][ni][2], c[mi][ni][3],
                             ah[mi][0], ah[mi][1], ah[mi][2], ah[mi][3],
                             bl[ni][0], bl[ni][1]);
                    MMA16816(c[mi][ni][0], c[mi][ni][1], c[mi][ni][2], c[mi][ni][3],
                             al[mi][0], al[mi][1], al[mi][2], al[mi][3],
                             bh[ni][0], bh[ni][1]);
                }
        }
        __syncthreads();   // all reads of buf[ch&1] done before it is re-staged
    }

    // distances in place of accumulators
#pragma unroll
    for (int mi = 0; mi < 2; mi++) {
        int i0 = (wm << 5) + (mi << 4) + g;
#pragma unroll
        for (int ni = 0; ni < 8; ni++) {
            int j0 = (wn << 6) + (ni << 3) + (tg << 1);
            c[mi][ni][0] = sqrtf(fmaxf(sNi[i0]     + sNj[j0]     - 2.f * c[mi][ni][0], 0.f));
            c[mi][ni][1] = sqrtf(fmaxf(sNi[i0]     + sNj[j0 + 1] - 2.f * c[mi][ni][1], 0.f));
            c[mi][ni][2] = sqrtf(fmaxf(sNi[i0 + 8] + sNj[j0]     - 2.f * c[mi][ni][2], 0.f));
            c[mi][ni][3] = sqrtf(fmaxf(sNi[i0 + 8] + sNj[j0 + 1] - 2.f * c[mi][ni][3], 0.f));
        }
    }

    float*  sSR = reinterpret_cast<float*>(smem + OFF_SR);   // stride 17
    float2* sTR = reinterpret_cast<float2*>(smem + OFF_TR);  // stride 17
    float*  sSC = reinterpret_cast<float*>(smem + OFF_SC);   // stride 17
    float2* sTC = reinterpret_cast<float2*>(smem + OFF_TC);  // stride 17

    if (diag) {
        // scatter same-class C values (classes are 16-aligned: class = idx>>4)
        float* sPos = reinterpret_cast<float*>(smem + OFF_SC);
#pragma unroll
        for (int mi = 0; mi < 2; mi++) {
            int ia = (wm << 5) + (mi << 4) + g, ib = ia + 8;
#pragma unroll
            for (int ni = 0; ni < 8; ni++) {
                int j0 = (wn << 6) + (ni << 3) + (tg << 1);
#pragma unroll
                for (int e = 0; e < 2; e++) {
                    int j = j0 + e;
                    if ((ia >> 4) == (j >> 4)) sPos[(ia << 4) + (j & 15)] = MARGIN + c[mi][ni][e];
                    if ((ib >> 4) == (j >> 4)) sPos[(ib << 4) + (j & 15)] = MARGIN + c[mi][ni][2 + e];
                }
            }
        }
        __syncthreads();
        // per-anchor rank sort + suffix sums; local tables + publish
        if (tid < 128) {
            float v[16];
#pragma unroll
            for (int k = 0; k < 16; k++) v[k] = sPos[(tid << 4) + k];
            float* ss = &sSR[tid * 17];
#pragma unroll
            for (int k = 0; k < 16; k++) {
                float vk = v[k];
                int r = 0;
#pragma unroll
                for (int jj = 0; jj < 16; jj++)
                    r += (int)((v[jj] < vk) | ((v[jj] == vk) & (jj < k)));
                ss[r] = vk;
            }
            size_t ab = (size_t)p * MM + by * 128 + tid;
            float run = 0.f;
            sTR[tid * 17 + 16] = make_float2(0.f, 0.f);
            g_tsuf[ab * 17 + 16] = make_float2(0.f, 0.f);
#pragma unroll
            for (int k = 15; k >= 0; k--) {
                run += ss[k];
                float2 tv = make_float2(run, (float)(16 - k));
                sTR[tid * 17 + k] = tv;
                g_tsuf[ab * 17 + k] = tv;
                g_tsort[ab * 16 + k] = ss[k];
            }
        }
        __threadfence();
        __syncthreads();
        if (tid == 0)
            asm volatile("st.release.gpu.global.b32 [%0], %1;"
                         :: "l"(&g_ready[bid]), "r"(1) : "memory");
    } else {
        // wait for both producer diag CTAs, then load tables
        if (tid == 0) {
            const int* f1 = &g_ready[(p << 2) + by];
            const int* f2 = &g_ready[(p << 2) + bx];
            int r1, r2;
            while (true) {
                asm volatile("ld.acquire.gpu.global.b32 %0, [%1];" : "=r"(r1) : "l"(f1) : "memory");
                asm volatile("ld.acquire.gpu.global.b32 %0, [%1];" : "=r"(r2) : "l"(f2) : "memory");
                if (r1 && r2) break;
                __nanosleep(128);
            }
        }
        __syncthreads();
        size_t rb16 = ((size_t)p * MM + by * 128) * 16;
        size_t rb17 = ((size_t)p * MM + by * 128) * 17;
        size_t cb16 = ((size_t)p * MM + bx * 128) * 16;
        size_t cb17 = ((size_t)p * MM + bx * 128) * 17;
        for (int q = tid; q < 2048; q += 256) {
            sSR[(q >> 4) * 17 + (q & 15)] = g_tsort[rb16 + q];
            sSC[(q >> 4) * 17 + (q & 15)] = g_tsort[cb16 + q];
        }
        for (int q = tid; q < 2176; q += 256) {
            sTR[q] = g_tsuf[rb17 + q];
            sTC[q] = g_tsuf[cb17 + q];
        }
        __syncthreads();
    }

    // hinge searches: row anchors hoisted; col S7/S15 hoisted per column
    const int abase = wm << 5;
    int aIdx[4] = {abase + g, abase + g + 8, abase + 16 + g, abase + 24 + g};
    const float*  SR[4]; const float2* TR[4];
    float S7[4], S15[4];
#pragma unroll
    for (int q = 0; q < 4; q++) {
        SR[q]  = &sSR[aIdx[q] * 17];
        TR[q]  = &sTR[aIdx[q] * 17];
        S7[q]  = SR[q][7];
        S15[q] = SR[q][15];
    }
    float aA = 0.f, aB = 0.f, aC = 0.f;
#pragma unroll
    for (int ni = 0; ni < 8; ni++) {
#pragma unroll
        for (int e = 0; e < 2; e++) {
            int j = (wn << 6) + (ni << 3) + (tg << 1) + e;
            float c7 = 0.f, c15 = 0.f;
            const float* SCj = &sSC[j * 17];
            const float2* TCj = &sTC[j * 17];
            if (!diag) { c7 = SCj[7]; c15 = SCj[15]; }
            int jc = j >> 4;
#pragma unroll
            for (int mi = 0; mi < 2; mi++) {
                float d0 = c[mi][ni][e];
                float d1 = c[mi][ni][2 + e];
                const int q0 = mi << 1, q1 = q0 + 1;
                bool ok0 = !diag || ((aIdx[q0] >> 4) != jc);
                bool ok1 = !diag || ((aIdx[q1] >> 4) != jc);
                if (ok0) search2(SR[q0], TR[q0], S7[q0], S15[q0], d0, aA, aB, aC);
                if (ok1) search2(SR[q1], TR[q1], S7[q1], S15[q1], d1, aA, aB, aC);
                if (!diag) {
                    search2(SCj, TCj, c7, c15, d0, aA, aB, aC);
                    search2(SCj, TCj, c7, c15, d1, aA, aB, aC);
                }
            }
        }
    }

    float loss = aA - aB, cnt = aC;
#pragma unroll
    for (int o = 16; o; o >>= 1) {
        loss += __shfl_xor_sync(0xffffffffu, loss, o);
        cnt  += __shfl_xor_sync(0xffffffffu, cnt, o);
    }
    float* sRed = reinterpret_cast<float*>(smem + OFF_RED);
    int*   sFlag = reinterpret_cast<int*>(smem + OFF_RED + 64);
    if (lane == 0) { sRed[w] = loss; sRed[8 + w] = cnt; }
    __syncthreads();
    if (tid == 0) {
        float L = 0.f, C = 0.f;
#pragma unroll
        for (int k = 0; k < 8; k++) { L += sRed[k]; C += sRed[8 + k]; }
        atomicAdd(&g_psum[p], L);
        atomicAdd(&g_pcnt[p], C);
        __threadfence();
        unsigned int t = atomicAdd(&g_ticket, 1u);
        *sFlag = (t == GRID_SZ - 1u);
    }
    __syncthreads();

    // last CTA: final reduce + write output + reset state for next launch
    if (*sFlag) {
        __threadfence();
        float a = 0.f, b = 0.f;
        if (tid < NP) {
            float cc = g_pcnt[tid], ssum = g_psum[tid];
            a = (cc > 0.f) ? ssum / fmaxf(cc, 1.f) : 0.f;
            b = cc;
        }
#pragma unroll
        for (int o = 16; o; o >>= 1) {
            a += __shfl_xor_sync(0xffffffffu, a, o);
            b += __shfl_xor_sync(0xffffffffu, b, o);
        }
        if (lane == 0 && w < 2) { sRed[w] = a; sRed[2 + w] = b; }
        __syncthreads();
        if (tid == 0) {
            out[0] = (sRed[0] + sRed[1]) / (float)NP;
            if (out_size > 1) out[1] = (sRed[2] + sRed[3]) / (float)NP;
            g_ticket = 0;
        }
        if (tid < NP) { g_psum[tid] = 0.f; g_pcnt[tid] = 0.f; }
        g_ready[tid] = 0;
    }
}

extern "C" void kernel_launch(void* const* d_in, const int* in_sizes, int n_in,
                              void* d_out, int out_size) {
    const float* feat = (const float*)d_in[0];
    (void)in_sizes; (void)n_in;

    cudaFuncSetAttribute(fused_kernel, cudaFuncAttributeMaxDynamicSharedMemorySize, SMEM_TOTAL);

    prep_kernel<<<4096, 256>>>(feat);
    fused_kernel<<<GRID_SZ, 256, SMEM_TOTAL>>>((float*)d_out, out_size);
}

// round 15
// speedup vs baseline: 1.0223x; 1.0020x over previous
#include <cuda_runtime.h>
#include <cuda_bf16.h>
#include <cstdint>
#include <math.h>

#define NP 64
#define MM 512
#define DD 256
#define MARGIN 0.2f
#define GRID_SZ 640

__device__ float  g_psum[NP];
__device__ float  g_pcnt[NP];
__device__ float  g_norm[NP * MM];
__device__ float  g_tsort[(size_t)NP * MM * 16];   // per-anchor sorted C values
__device__ float2 g_tsuf [(size_t)NP * MM * 17];   // per-anchor (suffix sum, count)
__device__ int    g_ready[NP * 4];                 // per (part, diag block) flag
__device__ unsigned int g_ticket;                  // last-CTA-done counter
// pre-split bf16 feature arrays (16 MB each)
__device__ __align__(16) uint16_t g_hi[(size_t)NP * MM * DD];
__device__ __align__(16) uint16_t g_lo[(size_t)NP * MM * DD];

// off-diagonal tile map (6 tiles of the 4x4 upper triangle)
__constant__ int c_oby[6] = {0,0,0,1,1,2};
__constant__ int c_obx[6] = {1,2,3,2,3,3};

// ---------------------------------------------------------------------------
__device__ __forceinline__ void split2(float x0, float x1, uint32_t& hi, uint32_t& lo) {
    uint32_t h;
    asm("cvt.rn.bf16x2.f32 %0, %1, %2;" : "=r"(h) : "f"(x1), "f"(x0));
    float h0 = __uint_as_float(h << 16);
    float h1 = __uint_as_float(h & 0xFFFF0000u);
    float r0 = x0 - h0, r1 = x1 - h1;
    asm("cvt.rn.bf16x2.f32 %0, %1, %2;" : "=r"(lo) : "f"(r1), "f"(r0));
    hi = h;
}

__device__ __forceinline__ uint32_t smem_u32(const void* p) {
    uint32_t a;
    asm("{ .reg .u64 t; cvta.to.shared.u64 t, %1; cvt.u32.u64 %0, t; }" : "=r"(a) : "l"(p));
    return a;
}

// ---------------------------------------------------------------------------
// prep: one pass over feat -> g_hi/g_lo bf16 splits + row norms.
// ---------------------------------------------------------------------------
__global__ __launch_bounds__(256) void prep_kernel(const float* __restrict__ feat) {
    int row  = (blockIdx.x << 3) + (threadIdx.x >> 5);
    int lane = threadIdx.x & 31;
    const float4* f = reinterpret_cast<const float4*>(feat + (size_t)row * DD);
    float4 v0 = f[lane << 1], v1 = f[(lane << 1) + 1];
    uint32_t h0, h1, h2, h3, l0, l1, l2, l3;
    split2(v0.x, v0.y, h0, l0); split2(v0.z, v0.w, h1, l1);
    split2(v1.x, v1.y, h2, l2); split2(v1.z, v1.w, h3, l3);
    size_t o = (size_t)row * DD + (lane << 3);
    *reinterpret_cast<uint4*>(g_hi + o) = make_uint4(h0, h1, h2, h3);
    *reinterpret_cast<uint4*>(g_lo + o) = make_uint4(l0, l1, l2, l3);
    float s = v0.x*v0.x + v0.y*v0.y + v0.z*v0.z + v0.w*v0.w
            + v1.x*v1.x + v1.y*v1.y + v1.z*v1.z + v1.w*v1.w;
#pragma unroll
    for (int ofs = 16; ofs; ofs >>= 1) s += __shfl_xor_sync(0xffffffffu, s, ofs);
    if (lane == 0) g_norm[row] = s;
}

#define MMA16816(c0,c1,c2,c3, a0,a1,a2,a3, b0,b1) \
    asm volatile("mma.sync.aligned.m16n8k16.row.col.f32.bf16.bf16.f32 " \
                 "{%0,%1,%2,%3}, {%4,%5,%6,%7}, {%8,%9}, {%0,%1,%2,%3};" \
                 : "+f"(c0), "+f"(c1), "+f"(c2), "+f"(c3) \
                 : "r"(a0), "r"(a1), "r"(a2), "r"(a3), "r"(b0), "r"(b1))

#define LDSM_X4(r0,r1,r2,r3, addr) \
    asm volatile("ldmatrix.sync.aligned.m8n8.x4.shared.b16 {%0,%1,%2,%3}, [%4];" \
        : "=r"(r0), "=r"(r1), "=r"(r2), "=r"(r3) : "r"(addr))

// SMEM layout. Double-buffered mainloop operands [0, 81920); epilogue tables
// overlay that region after the mainloop. Norms/reduce live above.
#define LDA 40
#define TILE_B (128 * LDA * 2)        // 10240 per bf16 tile
#define BUF_B  (4 * TILE_B)           // 40960 per buffer (AHI,ALO,BHI,BLO)
#define OFF_SR  0                     // float [128*17]
#define OFF_TR  8704                  // float2[128*17]
#define OFF_SC  26112                 // float [128*17] (diag: sPos 128*16)
#define OFF_TC  34816                 // float2[128*17] -> 52224
#define OFF_NRM 81920                 // 256 floats -> 82944
#define OFF_RED 82944                 // 16 floats + flag -> 83072
#define SMEM_TOTAL 83072

// stage one 128x32 bf16 tile (already split) global -> smem via cp.async
__device__ __forceinline__ void stage_tile(
    uint32_t sbase, const uint16_t* __restrict__ gsrc, int k0, int tid)
{
#pragma unroll
    for (int i = 0; i < 2; i++) {
        int id  = tid + (i << 8);       // 0..511 16B chunks
        int row = id >> 2, c = id & 3;
        uint32_t sa = sbase + row * (LDA * 2) + (c << 4);
        const void* ga = gsrc + (size_t)row * DD + k0 + (c << 3);
        asm volatile("cp.async.cg.shared.global [%0], [%1], 16;"
                     :: "r"(sa), "l"(ga) : "memory");
    }
}

// 4-step scalar binary search with hoisted S[7]/S[15]; idx in [0,16]
__device__ __forceinline__ void search2(
    const float* __restrict__ S, const float2* __restrict__ T,
    float s7, float s15, float d, float& aA, float& aB, float& aC)
{
    int idx = (s7 <= d) ? 8 : 0;
    idx += (S[idx + 3] <= d) ? 4 : 0;
    idx += (S[idx + 1] <= d) ? 2 : 0;
    idx += (S[idx]     <= d) ? 1 : 0;
    idx = (s15 <= d) ? 16 : idx;
    float2 t = T[idx];
    aA += t.x;
    aB  = fmaf(t.y, d, aB);
    aC += t.y;
}

// ---------------------------------------------------------------------------
// fused GEMM (pre-split bf16, cp.async + ldmatrix, low-liveness MMA order) +
// table build (diag) + hinge + last-CTA final reduce.
// ---------------------------------------------------------------------------
__global__ void __launch_bounds__(256, 2) fused_kernel(
    float* __restrict__ out, int out_size)
{
    extern __shared__ char smem[];
    const int tid = threadIdx.x;
    const int w = tid >> 5, lane = tid & 31;
    const int g = lane >> 2, tg = lane & 3;
    const int wm = w >> 1, wn = w & 1;
    const int bid = blockIdx.x;
    const bool diag = (bid < 256);
    int p, by, bx;
    if (diag) {
        p = bid >> 2; by = bx = bid & 3;
    } else {
        int q = bid - 256;
        p = q / 6;
        int t = q - p * 6;
        by = c_oby[t]; bx = c_obx[t];
    }
    const uint32_t sb = smem_u32(smem);

    float* sNi = reinterpret_cast<float*>(smem + OFF_NRM);
    float* sNj = diag ? sNi : (sNi + 128);
    if (tid < 128) {
        sNi[tid] = g_norm[p * MM + by * 128 + tid];
        if (!diag) sNj[tid] = g_norm[p * MM + bx * 128 + tid];
    }

    const size_t Aoff = ((size_t)p * MM + (size_t)by * 128) * DD;
    const size_t Boff = ((size_t)p * MM + (size_t)bx * 128) * DD;
    const uint16_t* Ahi = g_hi + Aoff;
    const uint16_t* Alo = g_lo + Aoff;
    const uint16_t* Bhi = g_hi + Boff;
    const uint16_t* Blo = g_lo + Boff;

    // ldmatrix per-lane offsets (bytes within a tile)
    const int aRowOff = ((wm << 5) + (lane & 15)) * (LDA * 2)
                      + ((lane & 16) ? 16 : 0);
    const int bRowOff = ((wn << 6) + (lane & 7) + ((lane & 16) ? 8 : 0)) * (LDA * 2)
                      + ((lane & 8) ? 16 : 0);

    float c[2][8][4];
#pragma unroll
    for (int mi = 0; mi < 2; mi++)
#pragma unroll
        for (int ni = 0; ni < 8; ni++)
#pragma unroll
            for (int r = 0; r < 4; r++) c[mi][ni][r] = 0.f;

    // preload chunk 0 into buffer 0
    stage_tile(sb, Ahi, 0, tid);
    stage_tile(sb + TILE_B, Alo, 0, tid);
    if (!diag) {
        stage_tile(sb + 2 * TILE_B, Bhi, 0, tid);
        stage_tile(sb + 3 * TILE_B, Blo, 0, tid);
    }
    asm volatile("cp.async.commit_group;" ::: "memory");

#pragma unroll 1
    for (int ch = 0; ch < 8; ch++) {
        if (ch < 7) {
            uint32_t bn = sb + ((ch + 1) & 1) * BUF_B;
            int k1 = (ch + 1) << 5;
            stage_tile(bn, Ahi, k1, tid);
            stage_tile(bn + TILE_B, Alo, k1, tid);
            if (!diag) {
                stage_tile(bn + 2 * TILE_B, Bhi, k1, tid);
                stage_tile(bn + 3 * TILE_B, Blo, k1, tid);
            }
            asm volatile("cp.async.commit_group;" ::: "memory");
            asm volatile("cp.async.wait_group 1;" ::: "memory");
        } else {
            asm volatile("cp.async.wait_group 0;" ::: "memory");
        }
        __syncthreads();   // chunk ch landed for all threads

        const uint32_t bA = sb + (ch & 1) * BUF_B;
        const uint32_t bB = diag ? bA : (bA + 2 * TILE_B);

#pragma unroll
        for (int ks = 0; ks < 2; ks++) {
            const int kOff = ks << 5;   // 32 bytes per k-step
            uint32_t ah[2][4], al[2][4];
#pragma unroll
            for (int mi = 0; mi < 2; mi++) {
                uint32_t aa = bA + aRowOff + mi * (16 * LDA * 2) + kOff;
                LDSM_X4(ah[mi][0], ah[mi][1], ah[mi][2], ah[mi][3], aa);
                LDSM_X4(al[mi][0], al[mi][1], al[mi][2], al[mi][3], aa + TILE_B);
            }
            // B fragments loaded per ni-pair and consumed immediately:
            // live set stays ~100 regs (no spills at the 128-reg cap)
#pragma unroll
            for (int n2 = 0; n2 < 4; n2++) {
                uint32_t ba = bB + bRowOff + n2 * (16 * LDA * 2) + kOff;
                uint32_t bh0, bh1, bh2, bh3, bl0, bl1, bl2, bl3;
                LDSM_X4(bh0, bh1, bh2, bh3, ba);
                LDSM_X4(bl0, bl1, bl2, bl3, ba + TILE_B);
                const int n0 = 2 * n2, n1 = n0 + 1;
#pragma unroll
                for (int mi = 0; mi < 2; mi++) {
                    MMA16816(c[mi][n0][0], c[mi][n0][1], c[mi][n0][2], c[mi][n0][3],
                             ah[mi][0], ah[mi][1], ah[mi][2], ah[mi][3], bh0, bh1);
                    MMA16816(c[mi][n0][0], c[mi][n0][1], c[mi][n0][2], c[mi][n0][3],
                             ah[mi][0], ah[mi][1], ah[mi][2], ah[mi][3], bl0, bl1);
                    MMA16816(c[mi][n0][0], c[mi][n0][1], c[mi][n0][2], c[mi][n0][3],
                             al[mi][0], al[mi][1], al[mi][2], al[mi][3], bh0, bh1);
                    MMA16816(c[mi][n1][0], c[mi][n1][1], c[mi][n1][2], c[mi][n1][3],
                             ah[mi][0], ah[mi][1], ah[mi][2], ah[mi][3], bh2, bh3);
                    MMA16816(c[mi][n1][0], c[mi][n1][1], c[mi][n1][2], c[mi][n1][3],
                             ah[mi][0], ah[mi][1], ah[mi][2], ah[mi][3], bl2, bl3);
                    MMA16816(c[mi][n1][0], c[mi][n1][1], c[mi][n1][2], c[mi][n1][3],
                             al[mi][0], al[mi][1], al[mi][2], al[mi][3], bh2, bh3);
                }
            }
        }
        __syncthreads();   // all reads of buf[ch&1] done before it is re-staged
    }

    // distances in place of accumulators
#pragma unroll
    for (int mi = 0; mi < 2; mi++) {
        int i0 = (wm << 5) + (mi << 4) + g;
#pragma unroll
        for (int ni = 0; ni < 8; ni++) {
            int j0 = (wn << 6) + (ni << 3) + (tg << 1);
            c[mi][ni][0] = sqrtf(fmaxf(sNi[i0]     + sNj[j0]     - 2.f * c[mi][ni][0], 0.f));
            c[mi][ni][1] = sqrtf(fmaxf(sNi[i0]     + sNj[j0 + 1] - 2.f * c[mi][ni][1], 0.f));
            c[mi][ni][2] = sqrtf(fmaxf(sNi[i0 + 8] + sNj[j0]     - 2.f * c[mi][ni][2], 0.f));
            c[mi][ni][3] = sqrtf(fmaxf(sNi[i0 + 8] + sNj[j0 + 1] - 2.f * c[mi][ni][3], 0.f));
        }
    }

    float*  sSR = reinterpret_cast<float*>(smem + OFF_SR);   // stride 17
    float2* sTR = reinterpret_cast<float2*>(smem + OFF_TR);  // stride 17
    float*  sSC = reinterpret_cast<float*>(smem + OFF_SC);   // stride 17
    float2* sTC = reinterpret_cast<float2*>(smem + OFF_TC);  // stride 17

    if (diag) {
        // scatter same-class C values (classes are 16-aligned: class = idx>>4)
        float* sPos = reinterpret_cast<float*>(smem + OFF_SC);
#pragma unroll
        for (int mi = 0; mi < 2; mi++) {
            int ia = (wm << 5) + (mi << 4) + g, ib = ia + 8;
#pragma unroll
            for (int ni = 0; ni < 8; ni++) {
                int j0 = (wn << 6) + (ni << 3) + (tg << 1);
#pragma unroll
                for (int e = 0; e < 2; e++) {
                    int j = j0 + e;
                    if ((ia >> 4) == (j >> 4)) sPos[(ia << 4) + (j & 15)] = MARGIN + c[mi][ni][e];
                    if ((ib >> 4) == (j >> 4)) sPos[(ib << 4) + (j & 15)] = MARGIN + c[mi][ni][2 + e];
                }
            }
        }
        __syncthreads();
        // per-anchor rank sort + suffix sums; local tables + publish
        if (tid < 128) {
            float v[16];
#pragma unroll
            for (int k = 0; k < 16; k++) v[k] = sPos[(tid << 4) + k];
            float* ss = &sSR[tid * 17];
#pragma unroll
            for (int k = 0; k < 16; k++) {
                float vk = v[k];
                int r = 0;
#pragma unroll
                for (int jj = 0; jj < 16; jj++)
                    r += (int)((v[jj] < vk) | ((v[jj] == vk) & (jj < k)));
                ss[r] = vk;
            }
            size_t ab = (size_t)p * MM + by * 128 + tid;
            float run = 0.f;
            sTR[tid * 17 + 16] = make_float2(0.f, 0.f);
            g_tsuf[ab * 17 + 16] = make_float2(0.f, 0.f);
#pragma unroll
            for (int k = 15; k >= 0; k--) {
                run += ss[k];
                float2 tv = make_float2(run, (float)(16 - k));
                sTR[tid * 17 + k] = tv;
                g_tsuf[ab * 17 + k] = tv;
                g_tsort[ab * 16 + k] = ss[k];
            }
        }
        __threadfence();
        __syncthreads();
        if (tid == 0)
            asm volatile("st.release.gpu.global.b32 [%0], %1;"
                         :: "l"(&g_ready[bid]), "r"(1) : "memory");
    } else {
        // wait for both producer diag CTAs, then load tables
        if (tid == 0) {
            const int* f1 = &g_ready[(p << 2) + by];
            const int* f2 = &g_ready[(p << 2) + bx];
            int r1, r2;
            while (true) {
                asm volatile("ld.acquire.gpu.global.b32 %0, [%1];" : "=r"(r1) : "l"(f1) : "memory");
                asm volatile("ld.acquire.gpu.global.b32 %0, [%1];" : "=r"(r2) : "l"(f2) : "memory");
                if (r1 && r2) break;
                __nanosleep(128);
            }
        }
        __syncthreads();
        size_t rb16 = ((size_t)p * MM + by * 128) * 16;
        size_t rb17 = ((size_t)p * MM + by * 128) * 17;
        size_t cb16 = ((size_t)p * MM + bx * 128) * 16;
        size_t cb17 = ((size_t)p * MM + bx * 128) * 17;
        for (int q = tid; q < 2048; q += 256) {
            sSR[(q >> 4) * 17 + (q & 15)] = g_tsort[rb16 + q];
            sSC[(q >> 4) * 17 + (q & 15)] = g_tsort[cb16 + q];
        }
        for (int q = tid; q < 2176; q += 256) {
            sTR[q] = g_tsuf[rb17 + q];
            sTC[q] = g_tsuf[cb17 + q];
        }
        __syncthreads();
    }

    // hinge searches: row anchors hoisted; col S7/S15 hoisted per column
    const int abase = wm << 5;
    int aIdx[4] = {abase + g, abase + g + 8, abase + 16 + g, abase + 24 + g};
    const float*  SR[4]; const float2* TR[4];
    float S7[4], S15[4];
#pragma unroll
    for (int q = 0; q < 4; q++) {
        SR[q]  = &sSR[aIdx[q] * 17];
        TR[q]  = &sTR[aIdx[q] * 17];
        S7[q]  = SR[q][7];
        S15[q] = SR[q][15];
    }
    float aA = 0.f, aB = 0.f, aC = 0.f;
#pragma unroll
    for (int ni = 0; ni < 8; ni++) {
#pragma unroll
        for (int e = 0; e < 2; e++) {
            int j = (wn << 6) + (ni << 3) + (tg << 1) + e;
            float c7 = 0.f, c15 = 0.f;
            const float* SCj = &sSC[j * 17];
            const float2* TCj = &sTC[j * 17];
            if (!diag) { c7 = SCj[7]; c15 = SCj[15]; }
            int jc = j >> 4;
#pragma unroll
            for (int mi = 0; mi < 2; mi++) {
                float d0 = c[mi][ni][e];
                float d1 = c[mi][ni][2 + e];
                const int q0 = mi << 1, q1 = q0 + 1;
                bool ok0 = !diag || ((aIdx[q0] >> 4) != jc);
                bool ok1 = !diag || ((aIdx[q1] >> 4) != jc);
                if (ok0) search2(SR[q0], TR[q0], S7[q0], S15[q0], d0, aA, aB, aC);
                if (ok1) search2(SR[q1], TR[q1], S7[q1], S15[q1], d1, aA, aB, aC);
                if (!diag) {
                    search2(SCj, TCj, c7, c15, d0, aA, aB, aC);
                    search2(SCj, TCj, c7, c15, d1, aA, aB, aC);
                }
            }
        }
    }

    float loss = aA - aB, cnt = aC;
#pragma unroll
    for (int o = 16; o; o >>= 1) {
        loss += __shfl_xor_sync(0xffffffffu, loss, o);
        cnt  += __shfl_xor_sync(0xffffffffu, cnt, o);
    }
    float* sRed = reinterpret_cast<float*>(smem + OFF_RED);
    int*   sFlag = reinterpret_cast<int*>(smem + OFF_RED + 64);
    if (lane == 0) { sRed[w] = loss; sRed[8 + w] = cnt; }
    __syncthreads();
    if (tid == 0) {
        float L = 0.f, C = 0.f;
#pragma unroll
        for (int k = 0; k < 8; k++) { L += sRed[k]; C += sRed[8 + k]; }
        atomicAdd(&g_psum[p], L);
        atomicAdd(&g_pcnt[p], C);
        __threadfence();
        unsigned int t = atomicAdd(&g_ticket, 1u);
        *sFlag = (t == GRID_SZ - 1u);
    }
    __syncthreads();

    // last CTA: final reduce + write output + reset state for next launch
    if (*sFlag) {
        __threadfence();
        float a = 0.f, b = 0.f;
        if (tid < NP) {
            float cc = g_pcnt[tid], ssum = g_psum[tid];
            a = (cc > 0.f) ? ssum / fmaxf(cc, 1.f) : 0.f;
            b = cc;
        }
#pragma unroll
        for (int o = 16; o; o >>= 1) {
            a += __shfl_xor_sync(0xffffffffu, a, o);
            b += __shfl_xor_sync(0xffffffffu, b, o);
        }
        if (lane == 0 && w < 2) { sRed[w] = a; sRed[2 + w] = b; }
        __syncthreads();
        if (tid == 0) {
            out[0] = (sRed[0] + sRed[1]) / (float)NP;
            if (out_size > 1) out[1] = (sRed[2] + sRed[3]) / (float)NP;
            g_ticket = 0;
        }
        if (tid < NP) { g_psum[tid] = 0.f; g_pcnt[tid] = 0.f; }
        g_ready[tid] = 0;
    }
}

extern "C" void kernel_launch(void* const* d_in, const int* in_sizes, int n_in,
                              void* d_out, int out_size) {
    const float* feat = (const float*)d_in[0];
    (void)in_sizes; (void)n_in;

    cudaFuncSetAttribute(fused_kernel, cudaFuncAttributeMaxDynamicSharedMemorySize, SMEM_TOTAL);

    prep_kernel<<<4096, 256>>>(feat);
    fused_kernel<<<GRID_SZ, 256, SMEM_TOTAL>>>((float*)d_out, out_size);
}

// round 16
// speedup vs baseline: 1.1655x; 1.1401x over previous
#include <cuda_runtime.h>
#include <cuda_bf16.h>
#include <cstdint>
#include <math.h>

#define NP 64
#define MM 512
#define DD 256
#define MARGIN 0.2f
#define GRID_SZ 640
#define NTHR 512

__device__ float  g_psum[NP];
__device__ float  g_pcnt[NP];
__device__ float  g_norm[NP * MM];
__device__ float  g_tsort[(size_t)NP * MM * 16];   // per-anchor sorted C values
__device__ float2 g_tsuf [(size_t)NP * MM * 17];   // per-anchor (suffix sum, count)
__device__ int    g_ready[NP * 4];                 // per (part, diag block) flag
__device__ unsigned int g_ticket;                  // last-CTA-done counter
// pre-split bf16 feature arrays (16 MB each)
__device__ __align__(16) uint16_t g_hi[(size_t)NP * MM * DD];
__device__ __align__(16) uint16_t g_lo[(size_t)NP * MM * DD];

// off-diagonal tile map (6 tiles of the 4x4 upper triangle)
__constant__ int c_oby[6] = {0,0,0,1,1,2};
__constant__ int c_obx[6] = {1,2,3,2,3,3};

// ---------------------------------------------------------------------------
__device__ __forceinline__ void split2(float x0, float x1, uint32_t& hi, uint32_t& lo) {
    uint32_t h;
    asm("cvt.rn.bf16x2.f32 %0, %1, %2;" : "=r"(h) : "f"(x1), "f"(x0));
    float h0 = __uint_as_float(h << 16);
    float h1 = __uint_as_float(h & 0xFFFF0000u);
    float r0 = x0 - h0, r1 = x1 - h1;
    asm("cvt.rn.bf16x2.f32 %0, %1, %2;" : "=r"(lo) : "f"(r1), "f"(r0));
    hi = h;
}

__device__ __forceinline__ uint32_t smem_u32(const void* p) {
    uint32_t a;
    asm("{ .reg .u64 t; cvta.to.shared.u64 t, %1; cvt.u32.u64 %0, t; }" : "=r"(a) : "l"(p));
    return a;
}

// ---------------------------------------------------------------------------
// prep: one pass over feat -> g_hi/g_lo bf16 splits + row norms.
// ---------------------------------------------------------------------------
__global__ __launch_bounds__(256) void prep_kernel(const float* __restrict__ feat) {
    int row  = (blockIdx.x << 3) + (threadIdx.x >> 5);
    int lane = threadIdx.x & 31;
    const float4* f = reinterpret_cast<const float4*>(feat + (size_t)row * DD);
    float4 v0 = f[lane << 1], v1 = f[(lane << 1) + 1];
    uint32_t h0, h1, h2, h3, l0, l1, l2, l3;
    split2(v0.x, v0.y, h0, l0); split2(v0.z, v0.w, h1, l1);
    split2(v1.x, v1.y, h2, l2); split2(v1.z, v1.w, h3, l3);
    size_t o = (size_t)row * DD + (lane << 3);
    *reinterpret_cast<uint4*>(g_hi + o) = make_uint4(h0, h1, h2, h3);
    *reinterpret_cast<uint4*>(g_lo + o) = make_uint4(l0, l1, l2, l3);
    float s = v0.x*v0.x + v0.y*v0.y + v0.z*v0.z + v0.w*v0.w
            + v1.x*v1.x + v1.y*v1.y + v1.z*v1.z + v1.w*v1.w;
#pragma unroll
    for (int ofs = 16; ofs; ofs >>= 1) s += __shfl_xor_sync(0xffffffffu, s, ofs);
    if (lane == 0) g_norm[row] = s;
}

#define MMA16816(c0,c1,c2,c3, a0,a1,a2,a3, b0,b1) \
    asm volatile("mma.sync.aligned.m16n8k16.row.col.f32.bf16.bf16.f32 " \
                 "{%0,%1,%2,%3}, {%4,%5,%6,%7}, {%8,%9}, {%0,%1,%2,%3};" \
                 : "+f"(c0), "+f"(c1), "+f"(c2), "+f"(c3) \
                 : "r"(a0), "r"(a1), "r"(a2), "r"(a3), "r"(b0), "r"(b1))

#define LDSM_X4(r0,r1,r2,r3, addr) \
    asm volatile("ldmatrix.sync.aligned.m8n8.x4.shared.b16 {%0,%1,%2,%3}, [%4];" \
        : "=r"(r0), "=r"(r1), "=r"(r2), "=r"(r3) : "r"(addr))

// SMEM layout. Double-buffered mainloop operands [0, 81920); epilogue tables
// overlay that region after the mainloop. Norms/reduce live above.
#define LDA 40
#define TILE_B (128 * LDA * 2)        // 10240 per bf16 tile
#define BUF_B  (4 * TILE_B)           // 40960 per buffer (AHI,ALO,BHI,BLO)
#define OFF_SR  0                     // float [128*17]
#define OFF_TR  8704                  // float2[128*17]
#define OFF_SC  26112                 // float [128*17] (diag: sPos 128*16)
#define OFF_TC  34816                 // float2[128*17] -> 52224
#define OFF_NRM 81920                 // 256 floats -> 82944
#define OFF_RED 82944                 // 32 floats + flag -> 83076
#define SMEM_TOTAL 83088

// stage one 128x32 bf16 tile (already split) global -> smem via cp.async
// 512 threads: exactly one 16B chunk per thread.
__device__ __forceinline__ void stage_tile(
    uint32_t sbase, const uint16_t* __restrict__ gsrc, int k0, int tid)
{
    int row = tid >> 2, c = tid & 3;
    uint32_t sa = sbase + row * (LDA * 2) + (c << 4);
    const void* ga = gsrc + (size_t)row * DD + k0 + (c << 3);
    asm volatile("cp.async.cg.shared.global [%0], [%1], 16;"
                 :: "r"(sa), "l"(ga) : "memory");
}

// 4-step scalar binary search with hoisted S[7]/S[15]; idx in [0,16]
__device__ __forceinline__ void search2(
    const float* __restrict__ S, const float2* __restrict__ T,
    float s7, float s15, float d, float& aA, float& aB, float& aC)
{
    int idx = (s7 <= d) ? 8 : 0;
    idx += (S[idx + 3] <= d) ? 4 : 0;
    idx += (S[idx + 1] <= d) ? 2 : 0;
    idx += (S[idx]     <= d) ? 1 : 0;
    idx = (s15 <= d) ? 16 : idx;
    float2 t = T[idx];
    aA += t.x;
    aB  = fmaf(t.y, d, aB);
    aC += t.y;
}

// ---------------------------------------------------------------------------
// fused GEMM + table build (diag) + hinge + last-CTA final reduce.
// 512 threads, 16 warps (4x4 grid, 32x32 warp tile) -> 32 accums/thread,
// 64-reg cap, 2 CTAs/SM = 32 warps/SM (2x the previous latency hiding).
// ---------------------------------------------------------------------------
__global__ void __launch_bounds__(NTHR, 2) fused_kernel(
    float* __restrict__ out, int out_size)
{
    extern __shared__ char smem[];
    const int tid = threadIdx.x;
    const int w = tid >> 5, lane = tid & 31;
    const int g = lane >> 2, tg = lane & 3;
    const int wm = w >> 2, wn = w & 3;
    const int bid = blockIdx.x;
    const bool diag = (bid < 256);
    int p, by, bx;
    if (diag) {
        p = bid >> 2; by = bx = bid & 3;
    } else {
        int q = bid - 256;
        p = q / 6;
        int t = q - p * 6;
        by = c_oby[t]; bx = c_obx[t];
    }
    const uint32_t sb = smem_u32(smem);

    float* sNi = reinterpret_cast<float*>(smem + OFF_NRM);
    float* sNj = diag ? sNi : (sNi + 128);
    if (tid < 128) {
        sNi[tid] = g_norm[p * MM + by * 128 + tid];
        if (!diag) sNj[tid] = g_norm[p * MM + bx * 128 + tid];
    }

    const size_t Aoff = ((size_t)p * MM + (size_t)by * 128) * DD;
    const size_t Boff = ((size_t)p * MM + (size_t)bx * 128) * DD;
    const uint16_t* Ahi = g_hi + Aoff;
    const uint16_t* Alo = g_lo + Aoff;
    const uint16_t* Bhi = g_hi + Boff;
    const uint16_t* Blo = g_lo + Boff;

    // ldmatrix per-lane offsets (bytes within a tile)
    const int aRowOff = ((wm << 5) + (lane & 15)) * (LDA * 2)
                      + ((lane & 16) ? 16 : 0);
    const int bRowOff = ((wn << 5) + (lane & 7) + ((lane & 16) ? 8 : 0)) * (LDA * 2)
                      + ((lane & 8) ? 16 : 0);

    float c[2][4][4];
#pragma unroll
    for (int mi = 0; mi < 2; mi++)
#pragma unroll
        for (int ni = 0; ni < 4; ni++)
#pragma unroll
            for (int r = 0; r < 4; r++) c[mi][ni][r] = 0.f;

    // preload chunk 0 into buffer 0
    stage_tile(sb, Ahi, 0, tid);
    stage_tile(sb + TILE_B, Alo, 0, tid);
    if (!diag) {
        stage_tile(sb + 2 * TILE_B, Bhi, 0, tid);
        stage_tile(sb + 3 * TILE_B, Blo, 0, tid);
    }
    asm volatile("cp.async.commit_group;" ::: "memory");

#pragma unroll 1
    for (int ch = 0; ch < 8; ch++) {
        if (ch < 7) {
            uint32_t bn = sb + ((ch + 1) & 1) * BUF_B;
            int k1 = (ch + 1) << 5;
            stage_tile(bn, Ahi, k1, tid);
            stage_tile(bn + TILE_B, Alo, k1, tid);
            if (!diag) {
                stage_tile(bn + 2 * TILE_B, Bhi, k1, tid);
                stage_tile(bn + 3 * TILE_B, Blo, k1, tid);
            }
            asm volatile("cp.async.commit_group;" ::: "memory");
            asm volatile("cp.async.wait_group 1;" ::: "memory");
        } else {
            asm volatile("cp.async.wait_group 0;" ::: "memory");
        }
        __syncthreads();   // chunk ch landed for all threads

        const uint32_t bA = sb + (ch & 1) * BUF_B;
        const uint32_t bB = diag ? bA : (bA + 2 * TILE_B);

#pragma unroll
        for (int ks = 0; ks < 2; ks++) {
            const int kOff = ks << 5;   // 32 bytes per k-step
#pragma unroll
            for (int mi = 0; mi < 2; mi++) {
                uint32_t a0, a1, a2, a3, x0, x1, x2, x3;
                uint32_t aa = bA + aRowOff + mi * (16 * LDA * 2) + kOff;
                LDSM_X4(a0, a1, a2, a3, aa);
                LDSM_X4(x0, x1, x2, x3, aa + TILE_B);
#pragma unroll
                for (int n2 = 0; n2 < 2; n2++) {
                    uint32_t ba = bB + bRowOff + n2 * (16 * LDA * 2) + kOff;
                    uint32_t bh0, bh1, bh2, bh3, bl0, bl1, bl2, bl3;
                    LDSM_X4(bh0, bh1, bh2, bh3, ba);
                    LDSM_X4(bl0, bl1, bl2, bl3, ba + TILE_B);
                    const int n0 = 2 * n2, n1 = n0 + 1;
                    MMA16816(c[mi][n0][0], c[mi][n0][1], c[mi][n0][2], c[mi][n0][3],
                             a0, a1, a2, a3, bh0, bh1);
                    MMA16816(c[mi][n0][0], c[mi][n0][1], c[mi][n0][2], c[mi][n0][3],
                             a0, a1, a2, a3, bl0, bl1);
                    MMA16816(c[mi][n0][0], c[mi][n0][1], c[mi][n0][2], c[mi][n0][3],
                             x0, x1, x2, x3, bh0, bh1);
                    MMA16816(c[mi][n1][0], c[mi][n1][1], c[mi][n1][2], c[mi][n1][3],
                             a0, a1, a2, a3, bh2, bh3);
                    MMA16816(c[mi][n1][0], c[mi][n1][1], c[mi][n1][2], c[mi][n1][3],
                             a0, a1, a2, a3, bl2, bl3);
                    MMA16816(c[mi][n1][0], c[mi][n1][1], c[mi][n1][2], c[mi][n1][3],
                             x0, x1, x2, x3, bh2, bh3);
                }
            }
        }
        __syncthreads();   // all reads of buf[ch&1] done before it is re-staged
    }

    // distances in place of accumulators
#pragma unroll
    for (int mi = 0; mi < 2; mi++) {
        int i0 = (wm << 5) + (mi << 4) + g;
#pragma unroll
        for (int ni = 0; ni < 4; ni++) {
            int j0 = (wn << 5) + (ni << 3) + (tg << 1);
            c[mi][ni][0] = sqrtf(fmaxf(sNi[i0]     + sNj[j0]     - 2.f * c[mi][ni][0], 0.f));
            c[mi][ni][1] = sqrtf(fmaxf(sNi[i0]     + sNj[j0 + 1] - 2.f * c[mi][ni][1], 0.f));
            c[mi][ni][2] = sqrtf(fmaxf(sNi[i0 + 8] + sNj[j0]     - 2.f * c[mi][ni][2], 0.f));
            c[mi][ni][3] = sqrtf(fmaxf(sNi[i0 + 8] + sNj[j0 + 1] - 2.f * c[mi][ni][3], 0.f));
        }
    }

    float*  sSR = reinterpret_cast<float*>(smem + OFF_SR);   // stride 17
    float2* sTR = reinterpret_cast<float2*>(smem + OFF_TR);  // stride 17
    float*  sSC = reinterpret_cast<float*>(smem + OFF_SC);   // stride 17
    float2* sTC = reinterpret_cast<float2*>(smem + OFF_TC);  // stride 17

    if (diag) {
        // scatter same-class C values (classes are 16-aligned: class = idx>>4)
        float* sPos = reinterpret_cast<float*>(smem + OFF_SC);
#pragma unroll
        for (int mi = 0; mi < 2; mi++) {
            int ia = (wm << 5) + (mi << 4) + g, ib = ia + 8;
#pragma unroll
            for (int ni = 0; ni < 4; ni++) {
                int j0 = (wn << 5) + (ni << 3) + (tg << 1);
#pragma unroll
                for (int e = 0; e < 2; e++) {
                    int j = j0 + e;
                    if ((ia >> 4) == (j >> 4)) sPos[(ia << 4) + (j & 15)] = MARGIN + c[mi][ni][e];
                    if ((ib >> 4) == (j >> 4)) sPos[(ib << 4) + (j & 15)] = MARGIN + c[mi][ni][2 + e];
                }
            }
        }
        __syncthreads();
        // per-anchor rank sort + suffix sums; local tables + publish
        if (tid < 128) {
            float v[16];
#pragma unroll
            for (int k = 0; k < 16; k++) v[k] = sPos[(tid << 4) + k];
            float* ss = &sSR[tid * 17];
#pragma unroll
            for (int k = 0; k < 16; k++) {
                float vk = v[k];
                int r = 0;
#pragma unroll
                for (int jj = 0; jj < 16; jj++)
                    r += (int)((v[jj] < vk) | ((v[jj] == vk) & (jj < k)));
                ss[r] = vk;
            }
            size_t ab = (size_t)p * MM + by * 128 + tid;
            float run = 0.f;
            sTR[tid * 17 + 16] = make_float2(0.f, 0.f);
            g_tsuf[ab * 17 + 16] = make_float2(0.f, 0.f);
#pragma unroll
            for (int k = 15; k >= 0; k--) {
                run += ss[k];
                float2 tv = make_float2(run, (float)(16 - k));
                sTR[tid * 17 + k] = tv;
                g_tsuf[ab * 17 + k] = tv;
                g_tsort[ab * 16 + k] = ss[k];
            }
        }
        __threadfence();
        __syncthreads();
        if (tid == 0)
            asm volatile("st.release.gpu.global.b32 [%0], %1;"
                         :: "l"(&g_ready[bid]), "r"(1) : "memory");
    } else {
        // wait for both producer diag CTAs, then load tables
        if (tid == 0) {
            const int* f1 = &g_ready[(p << 2) + by];
            const int* f2 = &g_ready[(p << 2) + bx];
            int r1, r2;
            while (true) {
                asm volatile("ld.acquire.gpu.global.b32 %0, [%1];" : "=r"(r1) : "l"(f1) : "memory");
                asm volatile("ld.acquire.gpu.global.b32 %0, [%1];" : "=r"(r2) : "l"(f2) : "memory");
                if (r1 && r2) break;
                __nanosleep(128);
            }
        }
        __syncthreads();
        size_t rb16 = ((size_t)p * MM + by * 128) * 16;
        size_t rb17 = ((size_t)p * MM + by * 128) * 17;
        size_t cb16 = ((size_t)p * MM + bx * 128) * 16;
        size_t cb17 = ((size_t)p * MM + bx * 128) * 17;
        for (int q = tid; q < 2048; q += NTHR) {
            sSR[(q >> 4) * 17 + (q & 15)] = g_tsort[rb16 + q];
            sSC[(q >> 4) * 17 + (q & 15)] = g_tsort[cb16 + q];
        }
        for (int q = tid; q < 2176; q += NTHR) {
            sTR[q] = g_tsuf[rb17 + q];
            sTC[q] = g_tsuf[cb17 + q];
        }
        __syncthreads();
    }

    // hinge searches: row anchors hoisted; col S7/S15 hoisted per column
    const int abase = wm << 5;
    int aIdx[4] = {abase + g, abase + g + 8, abase + 16 + g, abase + 24 + g};
    const float*  SR[4]; const float2* TR[4];
    float S7[4], S15[4];
#pragma unroll
    for (int q = 0; q < 4; q++) {
        SR[q]  = &sSR[aIdx[q] * 17];
        TR[q]  = &sTR[aIdx[q] * 17];
        S7[q]  = SR[q][7];
        S15[q] = SR[q][15];
    }
    float aA = 0.f, aB = 0.f, aC = 0.f;
#pragma unroll
    for (int ni = 0; ni < 4; ni++) {
#pragma unroll
        for (int e = 0; e < 2; e++) {
            int j = (wn << 5) + (ni << 3) + (tg << 1) + e;
            float c7 = 0.f, c15 = 0.f;
            const float* SCj = &sSC[j * 17];
            const float2* TCj = &sTC[j * 17];
            if (!diag) { c7 = SCj[7]; c15 = SCj[15]; }
            int jc = j >> 4;
#pragma unroll
            for (int mi = 0; mi < 2; mi++) {
                float d0 = c[mi][ni][e];
                float d1 = c[mi][ni][2 + e];
                const int q0 = mi << 1, q1 = q0 + 1;
                bool ok0 = !diag || ((aIdx[q0] >> 4) != jc);
                bool ok1 = !diag || ((aIdx[q1] >> 4) != jc);
                if (ok0) search2(SR[q0], TR[q0], S7[q0], S15[q0], d0, aA, aB, aC);
                if (ok1) search2(SR[q1], TR[q1], S7[q1], S15[q1], d1, aA, aB, aC);
                if (!diag) {
                    search2(SCj, TCj, c7, c15, d0, aA, aB, aC);
                    search2(SCj, TCj, c7, c15, d1, aA, aB, aC);
                }
            }
        }
    }

    float loss = aA - aB, cnt = aC;
#pragma unroll
    for (int o = 16; o; o >>= 1) {
        loss += __shfl_xor_sync(0xffffffffu, loss, o);
        cnt  += __shfl_xor_sync(0xffffffffu, cnt, o);
    }
    float* sRed = reinterpret_cast<float*>(smem + OFF_RED);
    int*   sFlag = reinterpret_cast<int*>(smem + OFF_RED + 128);
    if (lane == 0) { sRed[w] = loss; sRed[16 + w] = cnt; }
    __syncthreads();
    if (tid == 0) {
        float L = 0.f, C = 0.f;
#pragma unroll
        for (int k = 0; k < 16; k++) { L += sRed[k]; C += sRed[16 + k]; }
        atomicAdd(&g_psum[p], L);
        atomicAdd(&g_pcnt[p], C);
        __threadfence();
        unsigned int t = atomicAdd(&g_ticket, 1u);
        *sFlag = (t == GRID_SZ - 1u);
    }
    __syncthreads();

    // last CTA: final reduce + write output + reset state for next launch
    if (*sFlag) {
        __threadfence();
        float a = 0.f, b = 0.f;
        if (tid < NP) {
            float cc = g_pcnt[tid], ssum = g_psum[tid];
            a = (cc > 0.f) ? ssum / fmaxf(cc, 1.f) : 0.f;
            b = cc;
        }
#pragma unroll
        for (int o = 16; o; o >>= 1) {
            a += __shfl_xor_sync(0xffffffffu, a, o);
            b += __shfl_xor_sync(0xffffffffu, b, o);
        }
        if (lane == 0 && w < 2) { sRed[w] = a; sRed[2 + w] = b; }
        __syncthreads();
        if (tid == 0) {
            out[0] = (sRed[0] + sRed[1]) / (float)NP;
            if (out_size > 1) out[1] = (sRed[2] + sRed[3]) / (float)NP;
            g_ticket = 0;
        }
        if (tid < NP) { g_psum[tid] = 0.f; g_pcnt[tid] = 0.f; }
        if (tid < NP * 4) g_ready[tid] = 0;
    }
}

extern "C" void kernel_launch(void* const* d_in, const int* in_sizes, int n_in,
                              void* d_out, int out_size) {
    const float* feat = (const float*)d_in[0];
    (void)in_sizes; (void)n_in;

    cudaFuncSetAttribute(fused_kernel, cudaFuncAttributeMaxDynamicSharedMemorySize, SMEM_TOTAL);

    prep_kernel<<<4096, 256>>>(feat);
    fused_kernel<<<GRID_SZ, NTHR, SMEM_TOTAL>>>((float*)d_out, out_size);
}